// round 1
// baseline (speedup 1.0000x reference)
#include <cuda_runtime.h>
#include <math.h>

// Problem constants
#define BSZ   2
#define SEQ   2048
#define DIM   1024
#define NH    16
#define HD    64
#define DFF   4096
#define MROWS (BSZ * SEQ)        // 4096

// -------------------- device scratch (no allocs allowed) --------------------
__device__ float g_ln  [MROWS * DIM];        // 16 MB
__device__ float g_qkv [MROWS * 3 * DIM];    // 48 MB
__device__ float g_attn[MROWS * DIM];        // 16 MB
__device__ float g_x2  [MROWS * DIM];        // 16 MB
__device__ float g_fc  [MROWS * DFF];        // 64 MB

// ------------------------------ LayerNorm -----------------------------------
__global__ __launch_bounds__(256) void ln_kernel(
    const float* __restrict__ X, const float* __restrict__ sc,
    const float* __restrict__ bi, float* __restrict__ Y)
{
    const int row = blockIdx.x;
    const int tid = threadIdx.x;
    const float4* xr = reinterpret_cast<const float4*>(X + (size_t)row * DIM);
    float4 v = xr[tid];

    float s  = v.x + v.y + v.z + v.w;
    float s2 = v.x * v.x + v.y * v.y + v.z * v.z + v.w * v.w;

    // warp reduce
    #pragma unroll
    for (int o = 16; o > 0; o >>= 1) {
        s  += __shfl_xor_sync(0xffffffffu, s,  o);
        s2 += __shfl_xor_sync(0xffffffffu, s2, o);
    }
    __shared__ float sh[2][8];
    const int wid = tid >> 5, lane = tid & 31;
    if (lane == 0) { sh[0][wid] = s; sh[1][wid] = s2; }
    __syncthreads();
    s = 0.f; s2 = 0.f;
    #pragma unroll
    for (int i = 0; i < 8; i++) { s += sh[0][i]; s2 += sh[1][i]; }

    const float mean = s * (1.0f / DIM);
    const float var  = s2 * (1.0f / DIM) - mean * mean;
    const float rstd = rsqrtf(var + 1e-5f);

    const float4 sc4 = reinterpret_cast<const float4*>(sc)[tid];
    const float4 bi4 = reinterpret_cast<const float4*>(bi)[tid];
    float4 o;
    o.x = (v.x - mean) * rstd * sc4.x + bi4.x;
    o.y = (v.y - mean) * rstd * sc4.y + bi4.y;
    o.z = (v.z - mean) * rstd * sc4.z + bi4.z;
    o.w = (v.w - mean) * rstd * sc4.w + bi4.w;
    reinterpret_cast<float4*>(Y + (size_t)row * DIM)[tid] = o;
}

// ------------------------------- GELU ---------------------------------------
__device__ __forceinline__ float gelu_f(float x) {
    const float c = 0.7978845608028654f;
    float t = tanhf(c * (x + 0.044715f * x * x * x));
    return 0.5f * x * (1.0f + t);
}

// ------------------------------ SGEMM ----------------------------------------
// C[M,N] = A[M,K] @ B[K,N] + bias ( + epilogue )
// EPI: 0 = bias only, 1 = bias + gelu, 2 = bias + residual add
#define BM 128
#define BN 128
#define BK 8
#define TM 8
#define TN 8

template <int EPI>
__global__ __launch_bounds__(256) void sgemm_kernel(
    const float* __restrict__ A, const float* __restrict__ B,
    const float* __restrict__ bias, const float* __restrict__ res,
    float* __restrict__ C, int M, int N, int K)
{
    __shared__ float As[BK][BM];
    __shared__ float Bs[BK][BN];

    const int tid  = threadIdx.x;
    const int brow = blockIdx.y * BM;
    const int bcol = blockIdx.x * BN;

    // A tile load mapping: 128 rows x 8 k; one float4 per thread
    const int aRow = tid >> 1;
    const int aCol = (tid & 1) << 2;
    // B tile load mapping: 8 k rows x 128 cols; one float4 per thread
    const int bRow = tid >> 5;
    const int bCol = (tid & 31) << 2;

    const int tx = tid & 15;
    const int ty = tid >> 4;

    float acc[TM][TN];
    #pragma unroll
    for (int i = 0; i < TM; i++)
        #pragma unroll
        for (int j = 0; j < TN; j++) acc[i][j] = 0.f;

    const float* Aptr = A + (size_t)(brow + aRow) * K + aCol;
    const float* Bptr = B + (size_t)bRow * N + bcol + bCol;

    for (int k0 = 0; k0 < K; k0 += BK) {
        float4 a4 = *reinterpret_cast<const float4*>(Aptr);
        As[aCol + 0][aRow] = a4.x;
        As[aCol + 1][aRow] = a4.y;
        As[aCol + 2][aRow] = a4.z;
        As[aCol + 3][aRow] = a4.w;
        *reinterpret_cast<float4*>(&Bs[bRow][bCol]) =
            *reinterpret_cast<const float4*>(Bptr);
        __syncthreads();

        #pragma unroll
        for (int k = 0; k < BK; k++) {
            float ra[TM], rb[TN];
            *reinterpret_cast<float4*>(&ra[0]) = *reinterpret_cast<const float4*>(&As[k][ty * TM]);
            *reinterpret_cast<float4*>(&ra[4]) = *reinterpret_cast<const float4*>(&As[k][ty * TM + 4]);
            *reinterpret_cast<float4*>(&rb[0]) = *reinterpret_cast<const float4*>(&Bs[k][tx * TN]);
            *reinterpret_cast<float4*>(&rb[4]) = *reinterpret_cast<const float4*>(&Bs[k][tx * TN + 4]);
            #pragma unroll
            for (int i = 0; i < TM; i++)
                #pragma unroll
                for (int j = 0; j < TN; j++)
                    acc[i][j] += ra[i] * rb[j];
        }
        __syncthreads();
        Aptr += BK;
        Bptr += (size_t)BK * N;
    }

    // epilogue
    #pragma unroll
    for (int i = 0; i < TM; i++) {
        const int r = brow + ty * TM + i;
        const size_t rowoff = (size_t)r * N;
        #pragma unroll
        for (int j = 0; j < TN; j += 4) {
            const int c = bcol + tx * TN + j;
            const float4 b4 = *reinterpret_cast<const float4*>(&bias[c]);
            float4 o;
            o.x = acc[i][j + 0] + b4.x;
            o.y = acc[i][j + 1] + b4.y;
            o.z = acc[i][j + 2] + b4.z;
            o.w = acc[i][j + 3] + b4.w;
            if (EPI == 1) {
                o.x = gelu_f(o.x); o.y = gelu_f(o.y);
                o.z = gelu_f(o.z); o.w = gelu_f(o.w);
            }
            if (EPI == 2) {
                const float4 r4 = *reinterpret_cast<const float4*>(&res[rowoff + c]);
                o.x += r4.x; o.y += r4.y; o.z += r4.z; o.w += r4.w;
            }
            *reinterpret_cast<float4*>(&C[rowoff + c]) = o;
        }
    }
}

// ------------------------- Flash attention (causal) --------------------------
// qkv layout: [b*SEQ + s][3*DIM], q at col h*HD, k at DIM + h*HD, v at 2*DIM + h*HD
// out layout: [b*SEQ + s][DIM] at col h*HD
// Grid: (SEQ/64, BSZ*NH), 64 threads, 1 query row per thread.
__global__ __launch_bounds__(64) void attn_kernel(
    const float* __restrict__ qkv, float* __restrict__ out)
{
    __shared__ float Ks[64][64];
    __shared__ float Vs[64][64];
    __shared__ float Ss[64][64];   // Ss[j][tid]

    const int bh = blockIdx.y;
    const int b = bh >> 4;
    const int h = bh & 15;
    const int tid = threadIdx.x;
    const int m = blockIdx.x * 64 + tid;      // query position in sequence

    const float* qrow = qkv + (size_t)(b * SEQ + m) * (3 * DIM) + h * HD;
    float q[HD];
    #pragma unroll
    for (int i = 0; i < HD; i += 4) {
        float4 t = *reinterpret_cast<const float4*>(qrow + i);
        q[i + 0] = t.x * 0.125f;
        q[i + 1] = t.y * 0.125f;
        q[i + 2] = t.z * 0.125f;
        q[i + 3] = t.w * 0.125f;
    }

    float acc[HD];
    #pragma unroll
    for (int i = 0; i < HD; i++) acc[i] = 0.f;
    float mi = -1e30f, li = 0.f;

    const int ntiles = blockIdx.x + 1;   // causal: only tiles with j0 <= max query row
    for (int t = 0; t < ntiles; t++) {
        const int j0 = t * 64;
        __syncthreads();
        // cooperative K/V tile load: 1024 float4 per tile, 64 threads
        for (int f = tid; f < 64 * 16; f += 64) {
            const int r = f >> 4;
            const int c4 = (f & 15) << 2;
            const float* kp = qkv + (size_t)(b * SEQ + j0 + r) * (3 * DIM) + DIM + h * HD + c4;
            *reinterpret_cast<float4*>(&Ks[r][c4]) = *reinterpret_cast<const float4*>(kp);
            *reinterpret_cast<float4*>(&Vs[r][c4]) = *reinterpret_cast<const float4*>(kp + DIM);
        }
        __syncthreads();

        // pass 1: scores + running max
        float mnew = mi;
        #pragma unroll 4
        for (int j = 0; j < 64; j++) {
            float s = 0.f;
            const float4* kr = reinterpret_cast<const float4*>(&Ks[j][0]);
            #pragma unroll
            for (int d4 = 0; d4 < 16; d4++) {
                float4 kv = kr[d4];
                s += q[4 * d4 + 0] * kv.x + q[4 * d4 + 1] * kv.y
                   + q[4 * d4 + 2] * kv.z + q[4 * d4 + 3] * kv.w;
            }
            if (j0 + j > m) s = -1e30f;
            Ss[j][tid] = s;
            mnew = fmaxf(mnew, s);
        }

        // rescale old state
        const float corr = __expf(mi - mnew);
        li *= corr;
        #pragma unroll
        for (int d = 0; d < HD; d++) acc[d] *= corr;

        // pass 2: probs + PV accumulate
        #pragma unroll 2
        for (int j = 0; j < 64; j++) {
            const float p = __expf(Ss[j][tid] - mnew);
            li += p;
            const float4* vr = reinterpret_cast<const float4*>(&Vs[j][0]);
            #pragma unroll
            for (int d4 = 0; d4 < 16; d4++) {
                float4 vv = vr[d4];
                acc[4 * d4 + 0] += p * vv.x;
                acc[4 * d4 + 1] += p * vv.y;
                acc[4 * d4 + 2] += p * vv.z;
                acc[4 * d4 + 3] += p * vv.w;
            }
        }
        mi = mnew;
    }

    const float inv = 1.0f / li;
    float* op = out + (size_t)(b * SEQ + m) * DIM + h * HD;
    #pragma unroll
    for (int i = 0; i < HD; i += 4) {
        float4 o;
        o.x = acc[i + 0] * inv;
        o.y = acc[i + 1] * inv;
        o.z = acc[i + 2] * inv;
        o.w = acc[i + 3] * inv;
        *reinterpret_cast<float4*>(op + i) = o;
    }
}

// ------------------------------ launcher -------------------------------------
extern "C" void kernel_launch(void* const* d_in, const int* in_sizes, int n_in,
                              void* d_out, int out_size)
{
    (void)in_sizes; (void)n_in; (void)out_size;
    const float* x    = (const float*)d_in[0];
    // d_in[1] = causal mask (known statically; ignored)
    const float* ln1s = (const float*)d_in[2];
    const float* ln1b = (const float*)d_in[3];
    const float* ln2s = (const float*)d_in[4];
    const float* ln2b = (const float*)d_in[5];
    const float* wqkv = (const float*)d_in[6];
    const float* bqkv = (const float*)d_in[7];
    const float* wap  = (const float*)d_in[8];
    const float* bap  = (const float*)d_in[9];
    const float* wfc  = (const float*)d_in[10];
    const float* bfc  = (const float*)d_in[11];
    const float* wmp  = (const float*)d_in[12];
    const float* bmp  = (const float*)d_in[13];
    float* out = (float*)d_out;

    float *ln, *qkv, *attn, *x2, *fc;
    cudaGetSymbolAddress((void**)&ln,   g_ln);
    cudaGetSymbolAddress((void**)&qkv,  g_qkv);
    cudaGetSymbolAddress((void**)&attn, g_attn);
    cudaGetSymbolAddress((void**)&x2,   g_x2);
    cudaGetSymbolAddress((void**)&fc,   g_fc);

    // 1. LN1
    ln_kernel<<<MROWS, 256>>>(x, ln1s, ln1b, ln);
    // 2. QKV = ln @ w_qkv + b_qkv            [4096,1024]x[1024,3072]
    sgemm_kernel<0><<<dim3((3 * DIM) / BN, MROWS / BM), 256>>>(
        ln, wqkv, bqkv, nullptr, qkv, MROWS, 3 * DIM, DIM);
    // 3. causal flash attention
    attn_kernel<<<dim3(SEQ / 64, BSZ * NH), 64>>>(qkv, attn);
    // 4. x2 = x + attn @ w_attn_proj + b     [4096,1024]x[1024,1024]
    sgemm_kernel<2><<<dim3(DIM / BN, MROWS / BM), 256>>>(
        attn, wap, bap, x, x2, MROWS, DIM, DIM);
    // 5. LN2
    ln_kernel<<<MROWS, 256>>>(x2, ln2s, ln2b, ln);
    // 6. fc = gelu(ln @ w_fc + b_fc)         [4096,1024]x[1024,4096]
    sgemm_kernel<1><<<dim3(DFF / BN, MROWS / BM), 256>>>(
        ln, wfc, bfc, nullptr, fc, MROWS, DFF, DIM);
    // 7. out = x2 + fc @ w_mlp_proj + b      [4096,4096]x[4096,1024]
    sgemm_kernel<2><<<dim3(DIM / BN, MROWS / BM), 256>>>(
        fc, wmp, bmp, x2, out, MROWS, DIM, DFF);
}

// round 3
// speedup vs baseline: 2.1062x; 2.1062x over previous
#include <cuda_runtime.h>
#include <math.h>
#include <stdint.h>

// Problem constants
#define BSZ   2
#define SEQ   2048
#define DIM   1024
#define NH    16
#define HD    64
#define DFF   4096
#define MROWS (BSZ * SEQ)        // 4096

// -------------------- device scratch (no allocs allowed) --------------------
__device__ float g_ln   [MROWS * DIM];        // 16 MB (tf32-rounded)
__device__ float g_qkv  [MROWS * 3 * DIM];    // 48 MB (full fp32)
__device__ float g_attn [MROWS * DIM];        // 16 MB (tf32-rounded)
__device__ float g_x2   [MROWS * DIM];        // 16 MB (full fp32)
__device__ float g_fc   [MROWS * DFF];        // 64 MB (tf32-rounded)
__device__ float g_wqkvT[3 * DIM * DIM];      // [3D, D] tf32-rounded
__device__ float g_wapT [DIM * DIM];          // [D, D]
__device__ float g_wfcT [DFF * DIM];          // [DFF, D]
__device__ float g_wmpT [DIM * DFF];          // [D, DFF]

// ---------------------------- small helpers ----------------------------------
__device__ __forceinline__ float tf32r(float x) {
    float o;
    asm("cvt.rna.tf32.f32 %0, %1;" : "=f"(o) : "f"(x));
    return o;
}

__device__ __forceinline__ uint32_t smem_u32(const void* p) {
    uint32_t a;
    asm("{ .reg .u64 t; cvta.to.shared.u64 t, %1; cvt.u32.u64 %0, t; }"
        : "=r"(a) : "l"(p));
    return a;
}

#define CP_ASYNC16(dst_u32, src_ptr) \
    asm volatile("cp.async.cg.shared.global [%0], [%1], 16;" \
                 :: "r"(dst_u32), "l"(src_ptr))
#define CP_COMMIT() asm volatile("cp.async.commit_group;")
#define CP_WAIT1()  asm volatile("cp.async.wait_group 1;")
#define CP_WAIT0()  asm volatile("cp.async.wait_group 0;")

__device__ __forceinline__ void mma_tf32(
    float* c, uint32_t a0, uint32_t a1, uint32_t a2, uint32_t a3,
    uint32_t b0, uint32_t b1)
{
    asm volatile(
        "mma.sync.aligned.m16n8k8.row.col.f32.tf32.tf32.f32 "
        "{%0,%1,%2,%3}, {%4,%5,%6,%7}, {%8,%9}, {%0,%1,%2,%3};"
        : "+f"(c[0]), "+f"(c[1]), "+f"(c[2]), "+f"(c[3])
        : "r"(a0), "r"(a1), "r"(a2), "r"(a3), "r"(b0), "r"(b1));
}

// ------------------------------ LayerNorm -----------------------------------
__global__ __launch_bounds__(256) void ln_kernel(
    const float* __restrict__ X, const float* __restrict__ sc,
    const float* __restrict__ bi, float* __restrict__ Y)
{
    const int row = blockIdx.x;
    const int tid = threadIdx.x;
    const float4* xr = reinterpret_cast<const float4*>(X + (size_t)row * DIM);
    float4 v = xr[tid];

    float s  = v.x + v.y + v.z + v.w;
    float s2 = v.x * v.x + v.y * v.y + v.z * v.z + v.w * v.w;

    #pragma unroll
    for (int o = 16; o > 0; o >>= 1) {
        s  += __shfl_xor_sync(0xffffffffu, s,  o);
        s2 += __shfl_xor_sync(0xffffffffu, s2, o);
    }
    __shared__ float sh[2][8];
    const int wid = tid >> 5, lane = tid & 31;
    if (lane == 0) { sh[0][wid] = s; sh[1][wid] = s2; }
    __syncthreads();
    s = 0.f; s2 = 0.f;
    #pragma unroll
    for (int i = 0; i < 8; i++) { s += sh[0][i]; s2 += sh[1][i]; }

    const float mean = s * (1.0f / DIM);
    const float var  = s2 * (1.0f / DIM) - mean * mean;
    const float rstd = rsqrtf(var + 1e-5f);

    const float4 sc4 = reinterpret_cast<const float4*>(sc)[tid];
    const float4 bi4 = reinterpret_cast<const float4*>(bi)[tid];
    float4 o;
    o.x = tf32r((v.x - mean) * rstd * sc4.x + bi4.x);
    o.y = tf32r((v.y - mean) * rstd * sc4.y + bi4.y);
    o.z = tf32r((v.z - mean) * rstd * sc4.z + bi4.z);
    o.w = tf32r((v.w - mean) * rstd * sc4.w + bi4.w);
    reinterpret_cast<float4*>(Y + (size_t)row * DIM)[tid] = o;
}

// ------------------------------- GELU ---------------------------------------
__device__ __forceinline__ float gelu_f(float x) {
    const float c = 0.7978845608028654f;
    float t = tanhf(c * (x + 0.044715f * x * x * x));
    return 0.5f * x * (1.0f + t);
}

// ---------------------------- transpose (+tf32 round) -----------------------
__global__ __launch_bounds__(256) void transpose_kernel(
    const float* __restrict__ in, float* __restrict__ out, int R, int C)
{
    __shared__ float t[32][33];
    const int tx = threadIdx.x, ty = threadIdx.y;
    const int c = blockIdx.x * 32 + tx;
    const int r0 = blockIdx.y * 32;
    #pragma unroll
    for (int i = 0; i < 4; i++)
        t[ty + 8 * i][tx] = in[(size_t)(r0 + ty + 8 * i) * C + c];
    __syncthreads();
    const int n = blockIdx.x * 32 + ty;
    const int k = r0 + tx;
    #pragma unroll
    for (int i = 0; i < 4; i++)
        out[(size_t)(n + 8 * i) * R + k] = tf32r(t[tx][ty + 8 * i]);
}

// --------------------- tf32 mma.sync GEMM (128x256 CTA tile) -----------------
// C[M,N] = A[M,K] @ W[K,N] + bias (+ epilogue)
// A row-major [M,K] (tf32-rounded), Bt = W^T row-major [N,K] (tf32-rounded)
// EPI: 0 = bias, 1 = bias+gelu (output tf32-rounded), 2 = bias+residual
#define BM 128
#define BN 256
#define BK 32
#define LDK 36                      // BK + 4 pad (floats)
#define A_FLOATS (BM * LDK)         // 4608
#define B_FLOATS (BN * LDK)         // 9216
#define STAGE_FLOATS (A_FLOATS + B_FLOATS)  // 13824
#define SMEM_BYTES (2 * STAGE_FLOATS * 4)   // 110592

template <int EPI>
__global__ __launch_bounds__(256, 1)
void mma_gemm(const float* __restrict__ A, const float* __restrict__ Bt,
              const float* __restrict__ bias, const float* __restrict__ res,
              float* __restrict__ C, int M, int N, int K)
{
    extern __shared__ float smem[];

    const int tid  = threadIdx.x;
    const int wid  = tid >> 5;
    const int lane = tid & 31;
    const int g    = lane >> 2;     // groupID 0..7
    const int t4   = lane & 3;      // thread-in-group 0..3
    const int wm   = (wid >> 2) * 64;   // warp m offset (0/64)
    const int wn   = (wid & 3) * 64;    // warp n offset (0/64/128/192)
    const int brow = blockIdx.y * BM;
    const int bcol = blockIdx.x * BN;

    const uint32_t sbase = smem_u32(smem);

    const float* Ag = A  + (size_t)brow * K;
    const float* Bg = Bt + (size_t)bcol * K;

    // ---- async stage loader: 12 float4 per thread ----
    auto load_stage = [&](int stage, int k0) {
        const uint32_t sA = sbase + stage * (STAGE_FLOATS * 4);
        const uint32_t sB = sA + A_FLOATS * 4;
        #pragma unroll
        for (int i = 0; i < 4; i++) {               // A: 1024 float4
            const int idx = tid + 256 * i;
            const int row = idx >> 3;
            const int col = (idx & 7) << 2;
            CP_ASYNC16(sA + (row * LDK + col) * 4, Ag + (size_t)row * K + k0 + col);
        }
        #pragma unroll
        for (int i = 0; i < 8; i++) {               // B: 2048 float4
            const int idx = tid + 256 * i;
            const int row = idx >> 3;
            const int col = (idx & 7) << 2;
            CP_ASYNC16(sB + (row * LDK + col) * 4, Bg + (size_t)row * K + k0 + col);
        }
        CP_COMMIT();
    };

    float c[4][8][4];
    #pragma unroll
    for (int mi = 0; mi < 4; mi++)
        #pragma unroll
        for (int ni = 0; ni < 8; ni++)
            #pragma unroll
            for (int j = 0; j < 4; j++) c[mi][ni][j] = 0.f;

    const int KT = K / BK;
    load_stage(0, 0);

    for (int kt = 0; kt < KT; kt++) {
        if (kt + 1 < KT) { load_stage((kt + 1) & 1, (kt + 1) * BK); CP_WAIT1(); }
        else             { CP_WAIT0(); }
        __syncthreads();

        const float* Asf = smem + (kt & 1) * STAGE_FLOATS;
        const float* Bsf = Asf + A_FLOATS;

        #pragma unroll
        for (int ks = 0; ks < BK; ks += 8) {
            uint32_t a[4][4], b[8][2];
            #pragma unroll
            for (int mi = 0; mi < 4; mi++) {
                const int r0 = (wm + mi * 16 + g) * LDK + ks + t4;
                a[mi][0] = __float_as_uint(Asf[r0]);
                a[mi][1] = __float_as_uint(Asf[r0 + 8 * LDK]);
                a[mi][2] = __float_as_uint(Asf[r0 + 4]);
                a[mi][3] = __float_as_uint(Asf[r0 + 8 * LDK + 4]);
            }
            #pragma unroll
            for (int ni = 0; ni < 8; ni++) {
                const int r0 = (wn + ni * 8 + g) * LDK + ks + t4;
                b[ni][0] = __float_as_uint(Bsf[r0]);
                b[ni][1] = __float_as_uint(Bsf[r0 + 4]);
            }
            #pragma unroll
            for (int mi = 0; mi < 4; mi++)
                #pragma unroll
                for (int ni = 0; ni < 8; ni++)
                    mma_tf32(c[mi][ni], a[mi][0], a[mi][1], a[mi][2], a[mi][3],
                             b[ni][0], b[ni][1]);
        }
        __syncthreads();
    }

    // ------------------------------ epilogue ---------------------------------
    #pragma unroll
    for (int mi = 0; mi < 4; mi++) {
        #pragma unroll
        for (int half = 0; half < 2; half++) {
            const int row = brow + wm + mi * 16 + g + half * 8;
            float* crow = C + (size_t)row * N;
            const float* rrow = (EPI == 2) ? (res + (size_t)row * N) : nullptr;
            #pragma unroll
            for (int ni = 0; ni < 8; ni++) {
                const int col = bcol + wn + ni * 8 + t4 * 2;
                float v0 = c[mi][ni][half * 2 + 0] + bias[col];
                float v1 = c[mi][ni][half * 2 + 1] + bias[col + 1];
                if (EPI == 1) {
                    v0 = tf32r(gelu_f(v0));
                    v1 = tf32r(gelu_f(v1));
                }
                if (EPI == 2) {
                    v0 += rrow[col];
                    v1 += rrow[col + 1];
                }
                float2 o = make_float2(v0, v1);
                *reinterpret_cast<float2*>(crow + col) = o;
            }
        }
    }
}

// ------------------------- Flash attention (causal) --------------------------
__global__ __launch_bounds__(64) void attn_kernel(
    const float* __restrict__ qkv, float* __restrict__ out)
{
    __shared__ float Ks[64][64];
    __shared__ float Vs[64][64];
    __shared__ float Ss[64][64];

    const int bh = blockIdx.y;
    const int b = bh >> 4;
    const int h = bh & 15;
    const int tid = threadIdx.x;
    const int m = blockIdx.x * 64 + tid;

    const float* qrow = qkv + (size_t)(b * SEQ + m) * (3 * DIM) + h * HD;
    float q[HD];
    #pragma unroll
    for (int i = 0; i < HD; i += 4) {
        float4 t = *reinterpret_cast<const float4*>(qrow + i);
        q[i + 0] = t.x * 0.125f;
        q[i + 1] = t.y * 0.125f;
        q[i + 2] = t.z * 0.125f;
        q[i + 3] = t.w * 0.125f;
    }

    float acc[HD];
    #pragma unroll
    for (int i = 0; i < HD; i++) acc[i] = 0.f;
    float mi = -1e30f, li = 0.f;

    const int ntiles = blockIdx.x + 1;
    for (int t = 0; t < ntiles; t++) {
        const int j0 = t * 64;
        __syncthreads();
        for (int f = tid; f < 64 * 16; f += 64) {
            const int r = f >> 4;
            const int c4 = (f & 15) << 2;
            const float* kp = qkv + (size_t)(b * SEQ + j0 + r) * (3 * DIM) + DIM + h * HD + c4;
            *reinterpret_cast<float4*>(&Ks[r][c4]) = *reinterpret_cast<const float4*>(kp);
            *reinterpret_cast<float4*>(&Vs[r][c4]) = *reinterpret_cast<const float4*>(kp + DIM);
        }
        __syncthreads();

        float mnew = mi;
        #pragma unroll 4
        for (int j = 0; j < 64; j++) {
            float s = 0.f;
            const float4* kr = reinterpret_cast<const float4*>(&Ks[j][0]);
            #pragma unroll
            for (int d4 = 0; d4 < 16; d4++) {
                float4 kv = kr[d4];
                s += q[4 * d4 + 0] * kv.x + q[4 * d4 + 1] * kv.y
                   + q[4 * d4 + 2] * kv.z + q[4 * d4 + 3] * kv.w;
            }
            if (j0 + j > m) s = -1e30f;
            Ss[j][tid] = s;
            mnew = fmaxf(mnew, s);
        }

        const float corr = __expf(mi - mnew);
        li *= corr;
        #pragma unroll
        for (int d = 0; d < HD; d++) acc[d] *= corr;

        #pragma unroll 2
        for (int j = 0; j < 64; j++) {
            const float p = __expf(Ss[j][tid] - mnew);
            li += p;
            const float4* vr = reinterpret_cast<const float4*>(&Vs[j][0]);
            #pragma unroll
            for (int d4 = 0; d4 < 16; d4++) {
                float4 vv = vr[d4];
                acc[4 * d4 + 0] += p * vv.x;
                acc[4 * d4 + 1] += p * vv.y;
                acc[4 * d4 + 2] += p * vv.z;
                acc[4 * d4 + 3] += p * vv.w;
            }
        }
        mi = mnew;
    }

    const float inv = 1.0f / li;
    float* op = out + (size_t)(b * SEQ + m) * DIM + h * HD;
    #pragma unroll
    for (int i = 0; i < HD; i += 4) {
        float4 o;
        o.x = tf32r(acc[i + 0] * inv);   // feeds attn-proj GEMM (tf32 A operand)
        o.y = tf32r(acc[i + 1] * inv);
        o.z = tf32r(acc[i + 2] * inv);
        o.w = tf32r(acc[i + 3] * inv);
        *reinterpret_cast<float4*>(op + i) = o;
    }
}

// ------------------------------ launcher -------------------------------------
extern "C" void kernel_launch(void* const* d_in, const int* in_sizes, int n_in,
                              void* d_out, int out_size)
{
    (void)in_sizes; (void)n_in; (void)out_size;
    const float* x    = (const float*)d_in[0];
    const float* ln1s = (const float*)d_in[2];
    const float* ln1b = (const float*)d_in[3];
    const float* ln2s = (const float*)d_in[4];
    const float* ln2b = (const float*)d_in[5];
    const float* wqkv = (const float*)d_in[6];
    const float* bqkv = (const float*)d_in[7];
    const float* wap  = (const float*)d_in[8];
    const float* bap  = (const float*)d_in[9];
    const float* wfc  = (const float*)d_in[10];
    const float* bfc  = (const float*)d_in[11];
    const float* wmp  = (const float*)d_in[12];
    const float* bmp  = (const float*)d_in[13];
    float* out = (float*)d_out;

    float *ln, *qkv, *attn, *x2, *fc, *wqkvT, *wapT, *wfcT, *wmpT;
    cudaGetSymbolAddress((void**)&ln,    g_ln);
    cudaGetSymbolAddress((void**)&qkv,   g_qkv);
    cudaGetSymbolAddress((void**)&attn,  g_attn);
    cudaGetSymbolAddress((void**)&x2,    g_x2);
    cudaGetSymbolAddress((void**)&fc,    g_fc);
    cudaGetSymbolAddress((void**)&wqkvT, g_wqkvT);
    cudaGetSymbolAddress((void**)&wapT,  g_wapT);
    cudaGetSymbolAddress((void**)&wfcT,  g_wfcT);
    cudaGetSymbolAddress((void**)&wmpT,  g_wmpT);

    cudaFuncSetAttribute(mma_gemm<0>, cudaFuncAttributeMaxDynamicSharedMemorySize, SMEM_BYTES);
    cudaFuncSetAttribute(mma_gemm<1>, cudaFuncAttributeMaxDynamicSharedMemorySize, SMEM_BYTES);
    cudaFuncSetAttribute(mma_gemm<2>, cudaFuncAttributeMaxDynamicSharedMemorySize, SMEM_BYTES);

    dim3 tb(32, 8);
    // 0. transpose weights into K-major [N,K] with tf32 rounding
    transpose_kernel<<<dim3(3 * DIM / 32, DIM / 32), tb>>>(wqkv, wqkvT, DIM, 3 * DIM);
    transpose_kernel<<<dim3(DIM / 32, DIM / 32),     tb>>>(wap,  wapT,  DIM, DIM);
    transpose_kernel<<<dim3(DFF / 32, DIM / 32),     tb>>>(wfc,  wfcT,  DIM, DFF);
    transpose_kernel<<<dim3(DIM / 32, DFF / 32),     tb>>>(wmp,  wmpT,  DFF, DIM);

    // 1. LN1
    ln_kernel<<<MROWS, 256>>>(x, ln1s, ln1b, ln);
    // 2. QKV = ln @ w_qkv + b_qkv          [4096,1024] x [1024,3072]
    mma_gemm<0><<<dim3(3 * DIM / BN, MROWS / BM), 256, SMEM_BYTES>>>(
        ln, wqkvT, bqkv, nullptr, qkv, MROWS, 3 * DIM, DIM);
    // 3. causal flash attention
    attn_kernel<<<dim3(SEQ / 64, BSZ * NH), 64>>>(qkv, attn);
    // 4. x2 = x + attn @ w_attn_proj + b   [4096,1024] x [1024,1024]
    mma_gemm<2><<<dim3(DIM / BN, MROWS / BM), 256, SMEM_BYTES>>>(
        attn, wapT, bap, x, x2, MROWS, DIM, DIM);
    // 5. LN2
    ln_kernel<<<MROWS, 256>>>(x2, ln2s, ln2b, ln);
    // 6. fc = gelu(ln @ w_fc + b_fc)       [4096,1024] x [1024,4096]
    mma_gemm<1><<<dim3(DFF / BN, MROWS / BM), 256, SMEM_BYTES>>>(
        ln, wfcT, bfc, nullptr, fc, MROWS, DFF, DIM);
    // 7. out = x2 + fc @ w_mlp_proj + b    [4096,4096] x [4096,1024]
    mma_gemm<2><<<dim3(DIM / BN, MROWS / BM), 256, SMEM_BYTES>>>(
        fc, wmpT, bmp, x2, out, MROWS, DIM, DFF);
}

// round 4
// speedup vs baseline: 3.5757x; 1.6977x over previous
#include <cuda_runtime.h>
#include <math.h>
#include <stdint.h>

// Problem constants
#define BSZ   2
#define SEQ   2048
#define DIM   1024
#define NH    16
#define HD    64
#define DFF   4096
#define MROWS (BSZ * SEQ)        // 4096

// -------------------- device scratch (no allocs allowed) --------------------
__device__ float g_ln   [MROWS * DIM];
__device__ float g_qkv  [MROWS * 3 * DIM];
__device__ float g_attn [MROWS * DIM];
__device__ float g_x2   [MROWS * DIM];
__device__ float g_fc   [MROWS * DFF];
__device__ float g_wqkvT[3 * DIM * DIM];
__device__ float g_wapT [DIM * DIM];
__device__ float g_wfcT [DFF * DIM];
__device__ float g_wmpT [DIM * DFF];

// ---------------------------- small helpers ----------------------------------
__device__ __forceinline__ float tf32r(float x) {
    float o;
    asm("cvt.rna.tf32.f32 %0, %1;" : "=f"(o) : "f"(x));
    return o;
}

__device__ __forceinline__ uint32_t smem_u32(const void* p) {
    uint32_t a;
    asm("{ .reg .u64 t; cvta.to.shared.u64 t, %1; cvt.u32.u64 %0, t; }"
        : "=r"(a) : "l"(p));
    return a;
}

#define CP_ASYNC16(dst_u32, src_ptr) \
    asm volatile("cp.async.cg.shared.global [%0], [%1], 16;" \
                 :: "r"(dst_u32), "l"(src_ptr))
#define CP_COMMIT() asm volatile("cp.async.commit_group;")
#define CP_WAIT1()  asm volatile("cp.async.wait_group 1;")
#define CP_WAIT0()  asm volatile("cp.async.wait_group 0;")

__device__ __forceinline__ void mma_tf32(
    float* c, uint32_t a0, uint32_t a1, uint32_t a2, uint32_t a3,
    uint32_t b0, uint32_t b1)
{
    asm volatile(
        "mma.sync.aligned.m16n8k8.row.col.f32.tf32.tf32.f32 "
        "{%0,%1,%2,%3}, {%4,%5,%6,%7}, {%8,%9}, {%0,%1,%2,%3};"
        : "+f"(c[0]), "+f"(c[1]), "+f"(c[2]), "+f"(c[3])
        : "r"(a0), "r"(a1), "r"(a2), "r"(a3), "r"(b0), "r"(b1));
}

// ------------------------------ LayerNorm -----------------------------------
__global__ __launch_bounds__(256) void ln_kernel(
    const float* __restrict__ X, const float* __restrict__ sc,
    const float* __restrict__ bi, float* __restrict__ Y)
{
    const int row = blockIdx.x;
    const int tid = threadIdx.x;
    const float4* xr = reinterpret_cast<const float4*>(X + (size_t)row * DIM);
    float4 v = xr[tid];

    float s  = v.x + v.y + v.z + v.w;
    float s2 = v.x * v.x + v.y * v.y + v.z * v.z + v.w * v.w;

    #pragma unroll
    for (int o = 16; o > 0; o >>= 1) {
        s  += __shfl_xor_sync(0xffffffffu, s,  o);
        s2 += __shfl_xor_sync(0xffffffffu, s2, o);
    }
    __shared__ float sh[2][8];
    const int wid = tid >> 5, lane = tid & 31;
    if (lane == 0) { sh[0][wid] = s; sh[1][wid] = s2; }
    __syncthreads();
    s = 0.f; s2 = 0.f;
    #pragma unroll
    for (int i = 0; i < 8; i++) { s += sh[0][i]; s2 += sh[1][i]; }

    const float mean = s * (1.0f / DIM);
    const float var  = s2 * (1.0f / DIM) - mean * mean;
    const float rstd = rsqrtf(var + 1e-5f);

    const float4 sc4 = reinterpret_cast<const float4*>(sc)[tid];
    const float4 bi4 = reinterpret_cast<const float4*>(bi)[tid];
    float4 o;
    o.x = tf32r((v.x - mean) * rstd * sc4.x + bi4.x);
    o.y = tf32r((v.y - mean) * rstd * sc4.y + bi4.y);
    o.z = tf32r((v.z - mean) * rstd * sc4.z + bi4.z);
    o.w = tf32r((v.w - mean) * rstd * sc4.w + bi4.w);
    reinterpret_cast<float4*>(Y + (size_t)row * DIM)[tid] = o;
}

// ------------------------------- GELU ---------------------------------------
__device__ __forceinline__ float gelu_f(float x) {
    const float c = 0.7978845608028654f;
    float t = tanhf(c * (x + 0.044715f * x * x * x));
    return 0.5f * x * (1.0f + t);
}

// ---------------------------- transpose (+tf32 round) -----------------------
__global__ __launch_bounds__(256) void transpose_kernel(
    const float* __restrict__ in, float* __restrict__ out, int R, int C)
{
    __shared__ float t[32][33];
    const int tx = threadIdx.x, ty = threadIdx.y;
    const int c = blockIdx.x * 32 + tx;
    const int r0 = blockIdx.y * 32;
    #pragma unroll
    for (int i = 0; i < 4; i++)
        t[ty + 8 * i][tx] = in[(size_t)(r0 + ty + 8 * i) * C + c];
    __syncthreads();
    const int n = blockIdx.x * 32 + ty;
    const int k = r0 + tx;
    #pragma unroll
    for (int i = 0; i < 4; i++)
        out[(size_t)(n + 8 * i) * R + k] = tf32r(t[tx][ty + 8 * i]);
}

// --------------------- tf32 mma.sync GEMM (128x256 CTA tile) -----------------
#define BM 128
#define BN 256
#define BK 32
#define LDK 36
#define A_FLOATS (BM * LDK)
#define B_FLOATS (BN * LDK)
#define STAGE_FLOATS (A_FLOATS + B_FLOATS)
#define SMEM_BYTES (2 * STAGE_FLOATS * 4)

template <int EPI>
__global__ __launch_bounds__(256, 1)
void mma_gemm(const float* __restrict__ A, const float* __restrict__ Bt,
              const float* __restrict__ bias, const float* __restrict__ res,
              float* __restrict__ C, int M, int N, int K)
{
    extern __shared__ float smem[];

    const int tid  = threadIdx.x;
    const int wid  = tid >> 5;
    const int lane = tid & 31;
    const int g    = lane >> 2;
    const int t4   = lane & 3;
    const int wm   = (wid >> 2) * 64;
    const int wn   = (wid & 3) * 64;
    const int brow = blockIdx.y * BM;
    const int bcol = blockIdx.x * BN;

    const uint32_t sbase = smem_u32(smem);

    const float* Ag = A  + (size_t)brow * K;
    const float* Bg = Bt + (size_t)bcol * K;

    auto load_stage = [&](int stage, int k0) {
        const uint32_t sA = sbase + stage * (STAGE_FLOATS * 4);
        const uint32_t sB = sA + A_FLOATS * 4;
        #pragma unroll
        for (int i = 0; i < 4; i++) {
            const int idx = tid + 256 * i;
            const int row = idx >> 3;
            const int col = (idx & 7) << 2;
            CP_ASYNC16(sA + (row * LDK + col) * 4, Ag + (size_t)row * K + k0 + col);
        }
        #pragma unroll
        for (int i = 0; i < 8; i++) {
            const int idx = tid + 256 * i;
            const int row = idx >> 3;
            const int col = (idx & 7) << 2;
            CP_ASYNC16(sB + (row * LDK + col) * 4, Bg + (size_t)row * K + k0 + col);
        }
        CP_COMMIT();
    };

    float c[4][8][4];
    #pragma unroll
    for (int mi = 0; mi < 4; mi++)
        #pragma unroll
        for (int ni = 0; ni < 8; ni++)
            #pragma unroll
            for (int j = 0; j < 4; j++) c[mi][ni][j] = 0.f;

    const int KT = K / BK;
    load_stage(0, 0);

    for (int kt = 0; kt < KT; kt++) {
        if (kt + 1 < KT) { load_stage((kt + 1) & 1, (kt + 1) * BK); CP_WAIT1(); }
        else             { CP_WAIT0(); }
        __syncthreads();

        const float* Asf = smem + (kt & 1) * STAGE_FLOATS;
        const float* Bsf = Asf + A_FLOATS;

        #pragma unroll
        for (int ks = 0; ks < BK; ks += 8) {
            uint32_t a[4][4], b[8][2];
            #pragma unroll
            for (int mi = 0; mi < 4; mi++) {
                const int r0 = (wm + mi * 16 + g) * LDK + ks + t4;
                a[mi][0] = __float_as_uint(Asf[r0]);
                a[mi][1] = __float_as_uint(Asf[r0 + 8 * LDK]);
                a[mi][2] = __float_as_uint(Asf[r0 + 4]);
                a[mi][3] = __float_as_uint(Asf[r0 + 8 * LDK + 4]);
            }
            #pragma unroll
            for (int ni = 0; ni < 8; ni++) {
                const int r0 = (wn + ni * 8 + g) * LDK + ks + t4;
                b[ni][0] = __float_as_uint(Bsf[r0]);
                b[ni][1] = __float_as_uint(Bsf[r0 + 4]);
            }
            #pragma unroll
            for (int mi = 0; mi < 4; mi++)
                #pragma unroll
                for (int ni = 0; ni < 8; ni++)
                    mma_tf32(c[mi][ni], a[mi][0], a[mi][1], a[mi][2], a[mi][3],
                             b[ni][0], b[ni][1]);
        }
        __syncthreads();
    }

    #pragma unroll
    for (int mi = 0; mi < 4; mi++) {
        #pragma unroll
        for (int half = 0; half < 2; half++) {
            const int row = brow + wm + mi * 16 + g + half * 8;
            float* crow = C + (size_t)row * N;
            const float* rrow = (EPI == 2) ? (res + (size_t)row * N) : nullptr;
            #pragma unroll
            for (int ni = 0; ni < 8; ni++) {
                const int col = bcol + wn + ni * 8 + t4 * 2;
                float v0 = c[mi][ni][half * 2 + 0] + bias[col];
                float v1 = c[mi][ni][half * 2 + 1] + bias[col + 1];
                if (EPI == 1) {
                    v0 = tf32r(gelu_f(v0));
                    v1 = tf32r(gelu_f(v1));
                }
                if (EPI == 2) {
                    v0 += rrow[col];
                    v1 += rrow[col + 1];
                }
                float2 o = make_float2(v0, v1);
                *reinterpret_cast<float2*>(crow + col) = o;
            }
        }
    }
}

// ------------------ tf32 tensor-core flash attention (causal) ----------------
// Block: 128 threads (4 warps), 64 query rows, key tiles of 64.
// Smem: Qs/Ks/Ps padded to 68 floats/row, Vs (natural [key][d]) padded to 72.
#define ALD 68
#define VLD 72
#define ATT_SMEM ((3 * 64 * ALD + 64 * VLD) * 4)   // 70656 bytes

__global__ __launch_bounds__(128, 1) void attn_tc_kernel(
    const float* __restrict__ qkv, float* __restrict__ out)
{
    extern __shared__ float asm_f[];
    float* Qs = asm_f;
    float* Ks = Qs + 64 * ALD;
    float* Ps = Ks + 64 * ALD;
    float* Vs = Ps + 64 * ALD;

    const int bh = blockIdx.y;
    const int b = bh >> 4;
    const int h = bh & 15;
    const int q0 = blockIdx.x * 64;
    const int tid = threadIdx.x;
    const int wid = tid >> 5;
    const int lane = tid & 31;
    const int g = lane >> 2;
    const int t4 = lane & 3;
    const int rowA = wid * 16 + g;
    const int rowB = rowA + 8;
    const int grA = q0 + rowA;
    const int grB = q0 + rowB;

    // load + scale + round Q tile
    for (int idx = tid; idx < 64 * 16; idx += 128) {
        const int r = idx >> 4, c4 = (idx & 15) << 2;
        const float4 v = *reinterpret_cast<const float4*>(
            qkv + (size_t)(b * SEQ + q0 + r) * (3 * DIM) + h * HD + c4);
        Qs[r * ALD + c4 + 0] = tf32r(v.x * 0.125f);
        Qs[r * ALD + c4 + 1] = tf32r(v.y * 0.125f);
        Qs[r * ALD + c4 + 2] = tf32r(v.z * 0.125f);
        Qs[r * ALD + c4 + 3] = tf32r(v.w * 0.125f);
    }

    float mi0 = -1e30f, mi1 = -1e30f, li0 = 0.f, li1 = 0.f;
    float o[8][4];
    #pragma unroll
    for (int ni = 0; ni < 8; ni++)
        #pragma unroll
        for (int j = 0; j < 4; j++) o[ni][j] = 0.f;

    const int ntiles = blockIdx.x + 1;
    for (int t = 0; t < ntiles; t++) {
        const int j0 = t * 64;
        __syncthreads();
        for (int idx = tid; idx < 64 * 16; idx += 128) {
            const int r = idx >> 4, c4 = (idx & 15) << 2;
            const float* kp = qkv + (size_t)(b * SEQ + j0 + r) * (3 * DIM)
                              + DIM + h * HD + c4;
            const float4 kv = *reinterpret_cast<const float4*>(kp);
            Ks[r * ALD + c4 + 0] = tf32r(kv.x);
            Ks[r * ALD + c4 + 1] = tf32r(kv.y);
            Ks[r * ALD + c4 + 2] = tf32r(kv.z);
            Ks[r * ALD + c4 + 3] = tf32r(kv.w);
            const float4 vv = *reinterpret_cast<const float4*>(kp + DIM);
            Vs[r * VLD + c4 + 0] = tf32r(vv.x);
            Vs[r * VLD + c4 + 1] = tf32r(vv.y);
            Vs[r * VLD + c4 + 2] = tf32r(vv.z);
            Vs[r * VLD + c4 + 3] = tf32r(vv.w);
        }
        __syncthreads();

        // ---- S = Q K^T via mma ----
        float s[8][4];
        #pragma unroll
        for (int ni = 0; ni < 8; ni++)
            #pragma unroll
            for (int j = 0; j < 4; j++) s[ni][j] = 0.f;

        #pragma unroll
        for (int kc = 0; kc < HD; kc += 8) {
            const uint32_t a0 = __float_as_uint(Qs[rowA * ALD + kc + t4]);
            const uint32_t a1 = __float_as_uint(Qs[rowB * ALD + kc + t4]);
            const uint32_t a2 = __float_as_uint(Qs[rowA * ALD + kc + t4 + 4]);
            const uint32_t a3 = __float_as_uint(Qs[rowB * ALD + kc + t4 + 4]);
            #pragma unroll
            for (int ni = 0; ni < 8; ni++) {
                const uint32_t b0 = __float_as_uint(Ks[(ni * 8 + g) * ALD + kc + t4]);
                const uint32_t b1 = __float_as_uint(Ks[(ni * 8 + g) * ALD + kc + t4 + 4]);
                mma_tf32(s[ni], a0, a1, a2, a3, b0, b1);
            }
        }

        // ---- causal mask + online softmax ----
        float mn0 = mi0, mn1 = mi1;
        #pragma unroll
        for (int ni = 0; ni < 8; ni++) {
            const int c0 = j0 + ni * 8 + 2 * t4;
            if (c0     > grA) s[ni][0] = -1e30f;
            if (c0 + 1 > grA) s[ni][1] = -1e30f;
            if (c0     > grB) s[ni][2] = -1e30f;
            if (c0 + 1 > grB) s[ni][3] = -1e30f;
            mn0 = fmaxf(mn0, fmaxf(s[ni][0], s[ni][1]));
            mn1 = fmaxf(mn1, fmaxf(s[ni][2], s[ni][3]));
        }
        mn0 = fmaxf(mn0, __shfl_xor_sync(0xffffffffu, mn0, 1));
        mn0 = fmaxf(mn0, __shfl_xor_sync(0xffffffffu, mn0, 2));
        mn1 = fmaxf(mn1, __shfl_xor_sync(0xffffffffu, mn1, 1));
        mn1 = fmaxf(mn1, __shfl_xor_sync(0xffffffffu, mn1, 2));

        const float corr0 = __expf(mi0 - mn0);
        const float corr1 = __expf(mi1 - mn1);
        mi0 = mn0; mi1 = mn1;

        float ls0 = 0.f, ls1 = 0.f;
        #pragma unroll
        for (int ni = 0; ni < 8; ni++) {
            const float p0 = __expf(s[ni][0] - mn0);
            const float p1 = __expf(s[ni][1] - mn0);
            const float p2 = __expf(s[ni][2] - mn1);
            const float p3 = __expf(s[ni][3] - mn1);
            ls0 += p0 + p1;
            ls1 += p2 + p3;
            const int cl = ni * 8 + 2 * t4;
            Ps[rowA * ALD + cl]     = tf32r(p0);
            Ps[rowA * ALD + cl + 1] = tf32r(p1);
            Ps[rowB * ALD + cl]     = tf32r(p2);
            Ps[rowB * ALD + cl + 1] = tf32r(p3);
        }
        ls0 += __shfl_xor_sync(0xffffffffu, ls0, 1);
        ls0 += __shfl_xor_sync(0xffffffffu, ls0, 2);
        ls1 += __shfl_xor_sync(0xffffffffu, ls1, 1);
        ls1 += __shfl_xor_sync(0xffffffffu, ls1, 2);
        li0 = li0 * corr0 + ls0;
        li1 = li1 * corr1 + ls1;

        #pragma unroll
        for (int ni = 0; ni < 8; ni++) {
            o[ni][0] *= corr0; o[ni][1] *= corr0;
            o[ni][2] *= corr1; o[ni][3] *= corr1;
        }
        __syncwarp();

        // ---- O += P V via mma (Ps rows are warp-private) ----
        #pragma unroll
        for (int kc = 0; kc < 8; kc++) {
            const uint32_t a0 = __float_as_uint(Ps[rowA * ALD + kc * 8 + t4]);
            const uint32_t a1 = __float_as_uint(Ps[rowB * ALD + kc * 8 + t4]);
            const uint32_t a2 = __float_as_uint(Ps[rowA * ALD + kc * 8 + t4 + 4]);
            const uint32_t a3 = __float_as_uint(Ps[rowB * ALD + kc * 8 + t4 + 4]);
            #pragma unroll
            for (int ni = 0; ni < 8; ni++) {
                const uint32_t b0 = __float_as_uint(Vs[(kc * 8 + t4) * VLD + ni * 8 + g]);
                const uint32_t b1 = __float_as_uint(Vs[(kc * 8 + t4 + 4) * VLD + ni * 8 + g]);
                mma_tf32(o[ni], a0, a1, a2, a3, b0, b1);
            }
        }
    }

    const float inv0 = 1.0f / li0;
    const float inv1 = 1.0f / li1;
    float* orow0 = out + (size_t)(b * SEQ + grA) * DIM + h * HD;
    float* orow1 = out + (size_t)(b * SEQ + grB) * DIM + h * HD;
    #pragma unroll
    for (int ni = 0; ni < 8; ni++) {
        const int d = ni * 8 + 2 * t4;
        float2 v0 = make_float2(tf32r(o[ni][0] * inv0), tf32r(o[ni][1] * inv0));
        float2 v1 = make_float2(tf32r(o[ni][2] * inv1), tf32r(o[ni][3] * inv1));
        *reinterpret_cast<float2*>(orow0 + d) = v0;
        *reinterpret_cast<float2*>(orow1 + d) = v1;
    }
}

// ------------------------------ launcher -------------------------------------
extern "C" void kernel_launch(void* const* d_in, const int* in_sizes, int n_in,
                              void* d_out, int out_size)
{
    (void)in_sizes; (void)n_in; (void)out_size;
    const float* x    = (const float*)d_in[0];
    const float* ln1s = (const float*)d_in[2];
    const float* ln1b = (const float*)d_in[3];
    const float* ln2s = (const float*)d_in[4];
    const float* ln2b = (const float*)d_in[5];
    const float* wqkv = (const float*)d_in[6];
    const float* bqkv = (const float*)d_in[7];
    const float* wap  = (const float*)d_in[8];
    const float* bap  = (const float*)d_in[9];
    const float* wfc  = (const float*)d_in[10];
    const float* bfc  = (const float*)d_in[11];
    const float* wmp  = (const float*)d_in[12];
    const float* bmp  = (const float*)d_in[13];
    float* out = (float*)d_out;

    float *ln, *qkv, *attn, *x2, *fc, *wqkvT, *wapT, *wfcT, *wmpT;
    cudaGetSymbolAddress((void**)&ln,    g_ln);
    cudaGetSymbolAddress((void**)&qkv,   g_qkv);
    cudaGetSymbolAddress((void**)&attn,  g_attn);
    cudaGetSymbolAddress((void**)&x2,    g_x2);
    cudaGetSymbolAddress((void**)&fc,    g_fc);
    cudaGetSymbolAddress((void**)&wqkvT, g_wqkvT);
    cudaGetSymbolAddress((void**)&wapT,  g_wapT);
    cudaGetSymbolAddress((void**)&wfcT,  g_wfcT);
    cudaGetSymbolAddress((void**)&wmpT,  g_wmpT);

    cudaFuncSetAttribute(mma_gemm<0>, cudaFuncAttributeMaxDynamicSharedMemorySize, SMEM_BYTES);
    cudaFuncSetAttribute(mma_gemm<1>, cudaFuncAttributeMaxDynamicSharedMemorySize, SMEM_BYTES);
    cudaFuncSetAttribute(mma_gemm<2>, cudaFuncAttributeMaxDynamicSharedMemorySize, SMEM_BYTES);
    cudaFuncSetAttribute(attn_tc_kernel, cudaFuncAttributeMaxDynamicSharedMemorySize, ATT_SMEM);

    dim3 tb(32, 8);
    transpose_kernel<<<dim3(3 * DIM / 32, DIM / 32), tb>>>(wqkv, wqkvT, DIM, 3 * DIM);
    transpose_kernel<<<dim3(DIM / 32, DIM / 32),     tb>>>(wap,  wapT,  DIM, DIM);
    transpose_kernel<<<dim3(DFF / 32, DIM / 32),     tb>>>(wfc,  wfcT,  DIM, DFF);
    transpose_kernel<<<dim3(DIM / 32, DFF / 32),     tb>>>(wmp,  wmpT,  DFF, DIM);

    ln_kernel<<<MROWS, 256>>>(x, ln1s, ln1b, ln);
    mma_gemm<0><<<dim3(3 * DIM / BN, MROWS / BM), 256, SMEM_BYTES>>>(
        ln, wqkvT, bqkv, nullptr, qkv, MROWS, 3 * DIM, DIM);
    attn_tc_kernel<<<dim3(SEQ / 64, BSZ * NH), 128, ATT_SMEM>>>(qkv, attn);
    mma_gemm<2><<<dim3(DIM / BN, MROWS / BM), 256, SMEM_BYTES>>>(
        attn, wapT, bap, x, x2, MROWS, DIM, DIM);
    ln_kernel<<<MROWS, 256>>>(x2, ln2s, ln2b, ln);
    mma_gemm<1><<<dim3(DFF / BN, MROWS / BM), 256, SMEM_BYTES>>>(
        ln, wfcT, bfc, nullptr, fc, MROWS, DFF, DIM);
    mma_gemm<2><<<dim3(DIM / BN, MROWS / BM), 256, SMEM_BYTES>>>(
        fc, wmpT, bmp, x2, out, MROWS, DIM, DFF);
}

// round 5
// speedup vs baseline: 5.8697x; 1.6415x over previous
#include <cuda_runtime.h>
#include <cuda_fp16.h>
#include <math.h>
#include <stdint.h>

// Problem constants
#define BSZ   2
#define SEQ   2048
#define DIM   1024
#define NH    16
#define HD    64
#define DFF   4096
#define MROWS (BSZ * SEQ)        // 4096

// -------------------- device scratch (no allocs allowed) --------------------
__device__ __half g_lnh  [MROWS * DIM];
__device__ __half g_qkvh [MROWS * 3 * DIM];
__device__ __half g_attnh[MROWS * DIM];
__device__ float  g_x2   [MROWS * DIM];
__device__ __half g_fch  [MROWS * DFF];
__device__ __half g_wqkvT[3 * DIM * DIM];   // [3D, D]
__device__ __half g_wapT [DIM * DIM];       // [D, D]
__device__ __half g_wfcT [DFF * DIM];       // [DFF, D]
__device__ __half g_wmpT [DIM * DFF];       // [D, DFF]

// ---------------------------- small helpers ----------------------------------
__device__ __forceinline__ uint32_t smem_u32(const void* p) {
    uint32_t a;
    asm("{ .reg .u64 t; cvta.to.shared.u64 t, %1; cvt.u32.u64 %0, t; }"
        : "=r"(a) : "l"(p));
    return a;
}

__device__ __forceinline__ uint32_t packh2(float lo, float hi) {
    __half2 h = __floats2half2_rn(lo, hi);
    return *reinterpret_cast<uint32_t*>(&h);
}

#define CP_ASYNC16(dst_u32, src_ptr) \
    asm volatile("cp.async.cg.shared.global [%0], [%1], 16;" \
                 :: "r"(dst_u32), "l"(src_ptr))
#define CP_COMMIT() asm volatile("cp.async.commit_group;")
#define CP_WAIT1()  asm volatile("cp.async.wait_group 1;")
#define CP_WAIT0()  asm volatile("cp.async.wait_group 0;")

__device__ __forceinline__ void mma_f16(
    float* c, uint32_t a0, uint32_t a1, uint32_t a2, uint32_t a3,
    uint32_t b0, uint32_t b1)
{
    asm volatile(
        "mma.sync.aligned.m16n8k16.row.col.f32.f16.f16.f32 "
        "{%0,%1,%2,%3}, {%4,%5,%6,%7}, {%8,%9}, {%0,%1,%2,%3};"
        : "+f"(c[0]), "+f"(c[1]), "+f"(c[2]), "+f"(c[3])
        : "r"(a0), "r"(a1), "r"(a2), "r"(a3), "r"(b0), "r"(b1));
}

// ------------------------------ LayerNorm (fp32 in, fp16 out) ---------------
__global__ __launch_bounds__(256) void ln_kernel(
    const float* __restrict__ X, const float* __restrict__ sc,
    const float* __restrict__ bi, __half* __restrict__ Y)
{
    const int row = blockIdx.x;
    const int tid = threadIdx.x;
    const float4* xr = reinterpret_cast<const float4*>(X + (size_t)row * DIM);
    float4 v = xr[tid];

    float s  = v.x + v.y + v.z + v.w;
    float s2 = v.x * v.x + v.y * v.y + v.z * v.z + v.w * v.w;

    #pragma unroll
    for (int o = 16; o > 0; o >>= 1) {
        s  += __shfl_xor_sync(0xffffffffu, s,  o);
        s2 += __shfl_xor_sync(0xffffffffu, s2, o);
    }
    __shared__ float sh[2][8];
    const int wid = tid >> 5, lane = tid & 31;
    if (lane == 0) { sh[0][wid] = s; sh[1][wid] = s2; }
    __syncthreads();
    s = 0.f; s2 = 0.f;
    #pragma unroll
    for (int i = 0; i < 8; i++) { s += sh[0][i]; s2 += sh[1][i]; }

    const float mean = s * (1.0f / DIM);
    const float var  = s2 * (1.0f / DIM) - mean * mean;
    const float rstd = rsqrtf(var + 1e-5f);

    const float4 sc4 = reinterpret_cast<const float4*>(sc)[tid];
    const float4 bi4 = reinterpret_cast<const float4*>(bi)[tid];
    uint2 o;
    o.x = packh2((v.x - mean) * rstd * sc4.x + bi4.x,
                 (v.y - mean) * rstd * sc4.y + bi4.y);
    o.y = packh2((v.z - mean) * rstd * sc4.z + bi4.z,
                 (v.w - mean) * rstd * sc4.w + bi4.w);
    reinterpret_cast<uint2*>(Y + (size_t)row * DIM)[tid] = o;
}

// ------------------------------- GELU ---------------------------------------
__device__ __forceinline__ float gelu_f(float x) {
    const float c = 0.7978845608028654f;
    float t = tanhf(c * (x + 0.044715f * x * x * x));
    return 0.5f * x * (1.0f + t);
}

// -------------------- transpose fp32 -> fp16 [R][C] -> [C][R] ----------------
__global__ __launch_bounds__(256) void transpose_kernel(
    const float* __restrict__ in, __half* __restrict__ out, int R, int C)
{
    __shared__ float t[32][33];
    const int tx = threadIdx.x, ty = threadIdx.y;
    const int c = blockIdx.x * 32 + tx;
    const int r0 = blockIdx.y * 32;
    #pragma unroll
    for (int i = 0; i < 4; i++)
        t[ty + 8 * i][tx] = in[(size_t)(r0 + ty + 8 * i) * C + c];
    __syncthreads();
    const int n = blockIdx.x * 32 + ty;
    const int k = r0 + tx;
    #pragma unroll
    for (int i = 0; i < 4; i++)
        out[(size_t)(n + 8 * i) * R + k] = __float2half(t[tx][ty + 8 * i]);
}

// --------------------- fp16 mma.sync GEMM (128x256 CTA tile) -----------------
// C[M,N] = A[M,K] @ W[K,N] + bias (+ epilogue), A half [M][K], Bt half [N][K]
// EPI: 0 = bias, cols<DIM scaled 1/8, half out   (QKV)
//      1 = bias + gelu, half out                 (FC)
//      2 = bias + residual, float out            (attn-proj, mlp-proj)
#define BM 128
#define BN 256
#define BK 64
#define LDKH 72
#define A_HALFS (BM * LDKH)                 // 9216
#define B_HALFS (BN * LDKH)                 // 18432
#define STAGE_HALFS (A_HALFS + B_HALFS)     // 27648
#define SMEM_BYTES (2 * STAGE_HALFS * 2)    // 110592

template <int EPI>
__global__ __launch_bounds__(256, 1)
void hgemm(const __half* __restrict__ A, const __half* __restrict__ Bt,
           const float* __restrict__ bias, const float* __restrict__ res,
           void* __restrict__ Cv, int M, int N, int K)
{
    extern __shared__ __half smem[];

    const int tid  = threadIdx.x;
    const int wid  = tid >> 5;
    const int lane = tid & 31;
    const int g    = lane >> 2;
    const int t4   = lane & 3;
    const int wm   = (wid >> 2) * 64;
    const int wn   = (wid & 3) * 64;
    const int brow = blockIdx.y * BM;
    const int bcol = blockIdx.x * BN;

    const uint32_t sbase = smem_u32(smem);

    const __half* Ag = A  + (size_t)brow * K;
    const __half* Bg = Bt + (size_t)bcol * K;

    auto load_stage = [&](int stage, int k0) {
        const uint32_t sA = sbase + stage * (STAGE_HALFS * 2);
        const uint32_t sB = sA + A_HALFS * 2;
        #pragma unroll
        for (int i = 0; i < 4; i++) {               // A: 1024 x 16B
            const int idx = tid + 256 * i;
            const int row = idx >> 3;
            const int col = (idx & 7) << 3;
            CP_ASYNC16(sA + (row * LDKH + col) * 2, Ag + (size_t)row * K + k0 + col);
        }
        #pragma unroll
        for (int i = 0; i < 8; i++) {               // B: 2048 x 16B
            const int idx = tid + 256 * i;
            const int row = idx >> 3;
            const int col = (idx & 7) << 3;
            CP_ASYNC16(sB + (row * LDKH + col) * 2, Bg + (size_t)row * K + k0 + col);
        }
        CP_COMMIT();
    };

    float c[4][8][4];
    #pragma unroll
    for (int mi = 0; mi < 4; mi++)
        #pragma unroll
        for (int ni = 0; ni < 8; ni++)
            #pragma unroll
            for (int j = 0; j < 4; j++) c[mi][ni][j] = 0.f;

    const int KT = K / BK;
    load_stage(0, 0);

    for (int kt = 0; kt < KT; kt++) {
        if (kt + 1 < KT) { load_stage((kt + 1) & 1, (kt + 1) * BK); CP_WAIT1(); }
        else             { CP_WAIT0(); }
        __syncthreads();

        const __half* Asf = smem + (kt & 1) * STAGE_HALFS;
        const __half* Bsf = Asf + A_HALFS;

        #pragma unroll
        for (int kc = 0; kc < 4; kc++) {            // 4 k-steps of 16
            uint32_t a[4][4], b[8][2];
            #pragma unroll
            for (int mi = 0; mi < 4; mi++) {
                const int r0 = (wm + mi * 16 + g) * LDKH + kc * 16 + 2 * t4;
                a[mi][0] = *reinterpret_cast<const uint32_t*>(&Asf[r0]);
                a[mi][1] = *reinterpret_cast<const uint32_t*>(&Asf[r0 + 8 * LDKH]);
                a[mi][2] = *reinterpret_cast<const uint32_t*>(&Asf[r0 + 8]);
                a[mi][3] = *reinterpret_cast<const uint32_t*>(&Asf[r0 + 8 * LDKH + 8]);
            }
            #pragma unroll
            for (int ni = 0; ni < 8; ni++) {
                const int r0 = (wn + ni * 8 + g) * LDKH + kc * 16 + 2 * t4;
                b[ni][0] = *reinterpret_cast<const uint32_t*>(&Bsf[r0]);
                b[ni][1] = *reinterpret_cast<const uint32_t*>(&Bsf[r0 + 8]);
            }
            #pragma unroll
            for (int mi = 0; mi < 4; mi++)
                #pragma unroll
                for (int ni = 0; ni < 8; ni++)
                    mma_f16(c[mi][ni], a[mi][0], a[mi][1], a[mi][2], a[mi][3],
                            b[ni][0], b[ni][1]);
        }
        __syncthreads();
    }

    // ------------------------------ epilogue ---------------------------------
    #pragma unroll
    for (int mi = 0; mi < 4; mi++) {
        #pragma unroll
        for (int half = 0; half < 2; half++) {
            const int row = brow + wm + mi * 16 + g + half * 8;
            #pragma unroll
            for (int ni = 0; ni < 8; ni++) {
                const int col = bcol + wn + ni * 8 + t4 * 2;
                float v0 = c[mi][ni][half * 2 + 0] + bias[col];
                float v1 = c[mi][ni][half * 2 + 1] + bias[col + 1];
                if (EPI == 0) {
                    if (col < DIM) { v0 *= 0.125f; v1 *= 0.125f; }
                    __half* crow = (__half*)Cv + (size_t)row * N;
                    *reinterpret_cast<uint32_t*>(crow + col) = packh2(v0, v1);
                } else if (EPI == 1) {
                    v0 = gelu_f(v0); v1 = gelu_f(v1);
                    __half* crow = (__half*)Cv + (size_t)row * N;
                    *reinterpret_cast<uint32_t*>(crow + col) = packh2(v0, v1);
                } else {
                    const float2 r2 = *reinterpret_cast<const float2*>(
                        res + (size_t)row * N + col);
                    float* crow = (float*)Cv + (size_t)row * N;
                    *reinterpret_cast<float2*>(crow + col) =
                        make_float2(v0 + r2.x, v1 + r2.y);
                }
            }
        }
    }
}

// ------------------ fp16 tensor-core flash attention (causal) ----------------
// Block: 128 threads (4 warps), 64 query rows, key tiles of 64.
// Q pre-scaled by 1/8 in QKV epilogue. Q/K natural [row][d], V transposed [d][key].
#define SLDH 72

__global__ __launch_bounds__(128, 1) void attn_tc_kernel(
    const __half* __restrict__ qkv, __half* __restrict__ out)
{
    __shared__ __half Qs[64 * SLDH];
    __shared__ __half Ks[64 * SLDH];
    __shared__ __half Vt[64 * SLDH];

    const int bh = blockIdx.y;
    const int b = bh >> 4;
    const int h = bh & 15;
    const int q0 = blockIdx.x * 64;
    const int tid = threadIdx.x;
    const int wid = tid >> 5;
    const int lane = tid & 31;
    const int g = lane >> 2;
    const int t4 = lane & 3;
    const int rowA = wid * 16 + g;
    const int rowB = rowA + 8;
    const int grA = q0 + rowA;
    const int grB = q0 + rowB;

    // load Q tile (already scaled)
    for (int idx = tid; idx < 512; idx += 128) {
        const int r = idx >> 3, c8 = (idx & 7) << 3;
        *reinterpret_cast<uint4*>(&Qs[r * SLDH + c8]) =
            *reinterpret_cast<const uint4*>(
                qkv + (size_t)(b * SEQ + q0 + r) * (3 * DIM) + h * HD + c8);
    }

    float mi0 = -1e30f, mi1 = -1e30f, li0 = 0.f, li1 = 0.f;
    float o[8][4];
    #pragma unroll
    for (int ni = 0; ni < 8; ni++)
        #pragma unroll
        for (int j = 0; j < 4; j++) o[ni][j] = 0.f;

    const int ntiles = blockIdx.x + 1;
    for (int t = 0; t < ntiles; t++) {
        const int j0 = t * 64;
        __syncthreads();
        for (int idx = tid; idx < 512; idx += 128) {
            const int r = idx >> 3, c8 = (idx & 7) << 3;
            const __half* kp = qkv + (size_t)(b * SEQ + j0 + r) * (3 * DIM)
                               + DIM + h * HD + c8;
            *reinterpret_cast<uint4*>(&Ks[r * SLDH + c8]) =
                *reinterpret_cast<const uint4*>(kp);
            // V transposed store: Vt[d][key]
            uint4 vv = *reinterpret_cast<const uint4*>(kp + DIM);
            const __half* vh = reinterpret_cast<const __half*>(&vv);
            #pragma unroll
            for (int i = 0; i < 8; i++)
                Vt[(c8 + i) * SLDH + r] = vh[i];
        }
        __syncthreads();

        // ---- S = Q K^T via fp16 mma ----
        float s[8][4];
        #pragma unroll
        for (int ni = 0; ni < 8; ni++)
            #pragma unroll
            for (int j = 0; j < 4; j++) s[ni][j] = 0.f;

        #pragma unroll
        for (int kc = 0; kc < 4; kc++) {
            const int qb = rowA * SLDH + kc * 16 + 2 * t4;
            const uint32_t a0 = *reinterpret_cast<const uint32_t*>(&Qs[qb]);
            const uint32_t a1 = *reinterpret_cast<const uint32_t*>(&Qs[qb + 8 * SLDH]);
            const uint32_t a2 = *reinterpret_cast<const uint32_t*>(&Qs[qb + 8]);
            const uint32_t a3 = *reinterpret_cast<const uint32_t*>(&Qs[qb + 8 * SLDH + 8]);
            #pragma unroll
            for (int ni = 0; ni < 8; ni++) {
                const int kb = (ni * 8 + g) * SLDH + kc * 16 + 2 * t4;
                const uint32_t b0 = *reinterpret_cast<const uint32_t*>(&Ks[kb]);
                const uint32_t b1 = *reinterpret_cast<const uint32_t*>(&Ks[kb + 8]);
                mma_f16(s[ni], a0, a1, a2, a3, b0, b1);
            }
        }

        // ---- causal mask + online softmax (fp32) ----
        float mn0 = mi0, mn1 = mi1;
        #pragma unroll
        for (int ni = 0; ni < 8; ni++) {
            const int c0 = j0 + ni * 8 + 2 * t4;
            if (c0     > grA) s[ni][0] = -1e30f;
            if (c0 + 1 > grA) s[ni][1] = -1e30f;
            if (c0     > grB) s[ni][2] = -1e30f;
            if (c0 + 1 > grB) s[ni][3] = -1e30f;
            mn0 = fmaxf(mn0, fmaxf(s[ni][0], s[ni][1]));
            mn1 = fmaxf(mn1, fmaxf(s[ni][2], s[ni][3]));
        }
        mn0 = fmaxf(mn0, __shfl_xor_sync(0xffffffffu, mn0, 1));
        mn0 = fmaxf(mn0, __shfl_xor_sync(0xffffffffu, mn0, 2));
        mn1 = fmaxf(mn1, __shfl_xor_sync(0xffffffffu, mn1, 1));
        mn1 = fmaxf(mn1, __shfl_xor_sync(0xffffffffu, mn1, 2));

        const float corr0 = __expf(mi0 - mn0);
        const float corr1 = __expf(mi1 - mn1);
        mi0 = mn0; mi1 = mn1;

        float p[8][4];
        float ls0 = 0.f, ls1 = 0.f;
        #pragma unroll
        for (int ni = 0; ni < 8; ni++) {
            p[ni][0] = __expf(s[ni][0] - mn0);
            p[ni][1] = __expf(s[ni][1] - mn0);
            p[ni][2] = __expf(s[ni][2] - mn1);
            p[ni][3] = __expf(s[ni][3] - mn1);
            ls0 += p[ni][0] + p[ni][1];
            ls1 += p[ni][2] + p[ni][3];
        }
        ls0 += __shfl_xor_sync(0xffffffffu, ls0, 1);
        ls0 += __shfl_xor_sync(0xffffffffu, ls0, 2);
        ls1 += __shfl_xor_sync(0xffffffffu, ls1, 1);
        ls1 += __shfl_xor_sync(0xffffffffu, ls1, 2);
        li0 = li0 * corr0 + ls0;
        li1 = li1 * corr1 + ls1;

        #pragma unroll
        for (int ni = 0; ni < 8; ni++) {
            o[ni][0] *= corr0; o[ni][1] *= corr0;
            o[ni][2] *= corr1; o[ni][3] *= corr1;
        }

        // ---- O += P V: P packed reg->reg (S frag layout == A frag layout) ----
        #pragma unroll
        for (int kc = 0; kc < 4; kc++) {
            const uint32_t a0 = packh2(p[2 * kc][0],     p[2 * kc][1]);
            const uint32_t a1 = packh2(p[2 * kc][2],     p[2 * kc][3]);
            const uint32_t a2 = packh2(p[2 * kc + 1][0], p[2 * kc + 1][1]);
            const uint32_t a3 = packh2(p[2 * kc + 1][2], p[2 * kc + 1][3]);
            #pragma unroll
            for (int ni = 0; ni < 8; ni++) {
                const int vb = (ni * 8 + g) * SLDH + kc * 16 + 2 * t4;
                const uint32_t b0 = *reinterpret_cast<const uint32_t*>(&Vt[vb]);
                const uint32_t b1 = *reinterpret_cast<const uint32_t*>(&Vt[vb + 8]);
                mma_f16(o[ni], a0, a1, a2, a3, b0, b1);
            }
        }
    }

    const float inv0 = 1.0f / li0;
    const float inv1 = 1.0f / li1;
    __half* orow0 = out + (size_t)(b * SEQ + grA) * DIM + h * HD;
    __half* orow1 = out + (size_t)(b * SEQ + grB) * DIM + h * HD;
    #pragma unroll
    for (int ni = 0; ni < 8; ni++) {
        const int d = ni * 8 + 2 * t4;
        *reinterpret_cast<uint32_t*>(orow0 + d) = packh2(o[ni][0] * inv0, o[ni][1] * inv0);
        *reinterpret_cast<uint32_t*>(orow1 + d) = packh2(o[ni][2] * inv1, o[ni][3] * inv1);
    }
}

// ------------------------------ launcher -------------------------------------
extern "C" void kernel_launch(void* const* d_in, const int* in_sizes, int n_in,
                              void* d_out, int out_size)
{
    (void)in_sizes; (void)n_in; (void)out_size;
    const float* x    = (const float*)d_in[0];
    const float* ln1s = (const float*)d_in[2];
    const float* ln1b = (const float*)d_in[3];
    const float* ln2s = (const float*)d_in[4];
    const float* ln2b = (const float*)d_in[5];
    const float* wqkv = (const float*)d_in[6];
    const float* bqkv = (const float*)d_in[7];
    const float* wap  = (const float*)d_in[8];
    const float* bap  = (const float*)d_in[9];
    const float* wfc  = (const float*)d_in[10];
    const float* bfc  = (const float*)d_in[11];
    const float* wmp  = (const float*)d_in[12];
    const float* bmp  = (const float*)d_in[13];
    float* out = (float*)d_out;

    __half *lnh, *qkvh, *attnh, *fch, *wqkvT, *wapT, *wfcT, *wmpT;
    float *x2;
    cudaGetSymbolAddress((void**)&lnh,   g_lnh);
    cudaGetSymbolAddress((void**)&qkvh,  g_qkvh);
    cudaGetSymbolAddress((void**)&attnh, g_attnh);
    cudaGetSymbolAddress((void**)&x2,    g_x2);
    cudaGetSymbolAddress((void**)&fch,   g_fch);
    cudaGetSymbolAddress((void**)&wqkvT, g_wqkvT);
    cudaGetSymbolAddress((void**)&wapT,  g_wapT);
    cudaGetSymbolAddress((void**)&wfcT,  g_wfcT);
    cudaGetSymbolAddress((void**)&wmpT,  g_wmpT);

    cudaFuncSetAttribute(hgemm<0>, cudaFuncAttributeMaxDynamicSharedMemorySize, SMEM_BYTES);
    cudaFuncSetAttribute(hgemm<1>, cudaFuncAttributeMaxDynamicSharedMemorySize, SMEM_BYTES);
    cudaFuncSetAttribute(hgemm<2>, cudaFuncAttributeMaxDynamicSharedMemorySize, SMEM_BYTES);

    dim3 tb(32, 8);
    // 0. transpose weights into K-major [N,K] fp16
    transpose_kernel<<<dim3(3 * DIM / 32, DIM / 32), tb>>>(wqkv, wqkvT, DIM, 3 * DIM);
    transpose_kernel<<<dim3(DIM / 32, DIM / 32),     tb>>>(wap,  wapT,  DIM, DIM);
    transpose_kernel<<<dim3(DFF / 32, DIM / 32),     tb>>>(wfc,  wfcT,  DIM, DFF);
    transpose_kernel<<<dim3(DIM / 32, DFF / 32),     tb>>>(wmp,  wmpT,  DFF, DIM);

    // 1. LN1 -> fp16
    ln_kernel<<<MROWS, 256>>>(x, ln1s, ln1b, lnh);
    // 2. QKV = ln @ w_qkv + b (Q cols pre-scaled by 1/8) -> fp16
    hgemm<0><<<dim3(3 * DIM / BN, MROWS / BM), 256, SMEM_BYTES>>>(
        lnh, wqkvT, bqkv, nullptr, qkvh, MROWS, 3 * DIM, DIM);
    // 3. causal flash attention (fp16 tensor cores) -> fp16
    attn_tc_kernel<<<dim3(SEQ / 64, BSZ * NH), 128>>>(qkvh, attnh);
    // 4. x2 = x + attn @ w_attn_proj + b -> fp32
    hgemm<2><<<dim3(DIM / BN, MROWS / BM), 256, SMEM_BYTES>>>(
        attnh, wapT, bap, x, x2, MROWS, DIM, DIM);
    // 5. LN2 -> fp16
    ln_kernel<<<MROWS, 256>>>(x2, ln2s, ln2b, lnh);
    // 6. fc = gelu(ln @ w_fc + b) -> fp16
    hgemm<1><<<dim3(DFF / BN, MROWS / BM), 256, SMEM_BYTES>>>(
        lnh, wfcT, bfc, nullptr, fch, MROWS, DFF, DIM);
    // 7. out = x2 + fc @ w_mlp_proj + b -> fp32
    hgemm<2><<<dim3(DIM / BN, MROWS / BM), 256, SMEM_BYTES>>>(
        fch, wmpT, bmp, x2, out, MROWS, DIM, DFF);
}

// round 6
// speedup vs baseline: 6.9274x; 1.1802x over previous
#include <cuda_runtime.h>
#include <cuda_fp16.h>
#include <math.h>
#include <stdint.h>

// Problem constants
#define BSZ   2
#define SEQ   2048
#define DIM   1024
#define NH    16
#define HD    64
#define DFF   4096
#define MROWS (BSZ * SEQ)        // 4096

// -------------------- device scratch (no allocs allowed) --------------------
__device__ __half g_lnh  [MROWS * DIM];
__device__ __half g_qkvh [MROWS * 3 * DIM];
__device__ __half g_attnh[MROWS * DIM];
__device__ float  g_x2   [MROWS * DIM];
__device__ __half g_fch  [MROWS * DFF];
__device__ __half g_wqkvT[3 * DIM * DIM];   // [3D, D]
__device__ __half g_wapT [DIM * DIM];       // [D, D]
__device__ __half g_wfcT [DFF * DIM];       // [DFF, D]
__device__ __half g_wmpT [DIM * DFF];       // [D, DFF]

// ---------------------------- small helpers ----------------------------------
__device__ __forceinline__ uint32_t smem_u32(const void* p) {
    uint32_t a;
    asm("{ .reg .u64 t; cvta.to.shared.u64 t, %1; cvt.u32.u64 %0, t; }"
        : "=r"(a) : "l"(p));
    return a;
}

__device__ __forceinline__ uint32_t packh2(float lo, float hi) {
    __half2 h = __floats2half2_rn(lo, hi);
    return *reinterpret_cast<uint32_t*>(&h);
}

#define CP_ASYNC16(dst_u32, src_ptr) \
    asm volatile("cp.async.cg.shared.global [%0], [%1], 16;" \
                 :: "r"(dst_u32), "l"(src_ptr))
#define CP_COMMIT() asm volatile("cp.async.commit_group;")
#define CP_WAIT1()  asm volatile("cp.async.wait_group 1;")

#define LDM_X4(r0, r1, r2, r3, addr) \
    asm volatile("ldmatrix.sync.aligned.m8n8.x4.shared.b16 {%0,%1,%2,%3}, [%4];" \
                 : "=r"(r0), "=r"(r1), "=r"(r2), "=r"(r3) : "r"(addr))
#define LDM_X4_T(r0, r1, r2, r3, addr) \
    asm volatile("ldmatrix.sync.aligned.m8n8.x4.trans.shared.b16 {%0,%1,%2,%3}, [%4];" \
                 : "=r"(r0), "=r"(r1), "=r"(r2), "=r"(r3) : "r"(addr))

__device__ __forceinline__ void mma_f16(
    float* c, uint32_t a0, uint32_t a1, uint32_t a2, uint32_t a3,
    uint32_t b0, uint32_t b1)
{
    asm volatile(
        "mma.sync.aligned.m16n8k16.row.col.f32.f16.f16.f32 "
        "{%0,%1,%2,%3}, {%4,%5,%6,%7}, {%8,%9}, {%0,%1,%2,%3};"
        : "+f"(c[0]), "+f"(c[1]), "+f"(c[2]), "+f"(c[3])
        : "r"(a0), "r"(a1), "r"(a2), "r"(a3), "r"(b0), "r"(b1));
}

// ------------------------------ LayerNorm (fp32 in, fp16 out) ---------------
__global__ __launch_bounds__(256) void ln_kernel(
    const float* __restrict__ X, const float* __restrict__ sc,
    const float* __restrict__ bi, __half* __restrict__ Y)
{
    const int row = blockIdx.x;
    const int tid = threadIdx.x;
    const float4* xr = reinterpret_cast<const float4*>(X + (size_t)row * DIM);
    float4 v = xr[tid];

    float s  = v.x + v.y + v.z + v.w;
    float s2 = v.x * v.x + v.y * v.y + v.z * v.z + v.w * v.w;

    #pragma unroll
    for (int o = 16; o > 0; o >>= 1) {
        s  += __shfl_xor_sync(0xffffffffu, s,  o);
        s2 += __shfl_xor_sync(0xffffffffu, s2, o);
    }
    __shared__ float sh[2][8];
    const int wid = tid >> 5, lane = tid & 31;
    if (lane == 0) { sh[0][wid] = s; sh[1][wid] = s2; }
    __syncthreads();
    s = 0.f; s2 = 0.f;
    #pragma unroll
    for (int i = 0; i < 8; i++) { s += sh[0][i]; s2 += sh[1][i]; }

    const float mean = s * (1.0f / DIM);
    const float var  = s2 * (1.0f / DIM) - mean * mean;
    const float rstd = rsqrtf(var + 1e-5f);

    const float4 sc4 = reinterpret_cast<const float4*>(sc)[tid];
    const float4 bi4 = reinterpret_cast<const float4*>(bi)[tid];
    uint2 o;
    o.x = packh2((v.x - mean) * rstd * sc4.x + bi4.x,
                 (v.y - mean) * rstd * sc4.y + bi4.y);
    o.y = packh2((v.z - mean) * rstd * sc4.z + bi4.z,
                 (v.w - mean) * rstd * sc4.w + bi4.w);
    reinterpret_cast<uint2*>(Y + (size_t)row * DIM)[tid] = o;
}

// ------------------------------- GELU ---------------------------------------
__device__ __forceinline__ float gelu_f(float x) {
    const float c = 0.7978845608028654f;
    float t = tanhf(c * (x + 0.044715f * x * x * x));
    return 0.5f * x * (1.0f + t);
}

// -------------------- transpose fp32 -> fp16 [R][C] -> [C][R] ----------------
__global__ __launch_bounds__(256) void transpose_kernel(
    const float* __restrict__ in, __half* __restrict__ out, int R, int C)
{
    __shared__ float t[32][33];
    const int tx = threadIdx.x, ty = threadIdx.y;
    const int c = blockIdx.x * 32 + tx;
    const int r0 = blockIdx.y * 32;
    #pragma unroll
    for (int i = 0; i < 4; i++)
        t[ty + 8 * i][tx] = in[(size_t)(r0 + ty + 8 * i) * C + c];
    __syncthreads();
    const int n = blockIdx.x * 32 + ty;
    const int k = r0 + tx;
    #pragma unroll
    for (int i = 0; i < 4; i++)
        out[(size_t)(n + 8 * i) * R + k] = __float2half(t[tx][ty + 8 * i]);
}

// --------------------- fp16 mma.sync GEMM (128x256 CTA tile) -----------------
// 3-stage cp.async pipeline, ldmatrix fragment loads, one sync per K-tile.
#define BM 128
#define BN 256
#define BK 64
#define LDKH 72
#define A_HALFS (BM * LDKH)
#define B_HALFS (BN * LDKH)
#define STAGE_HALFS (A_HALFS + B_HALFS)
#define STAGE_BYTES (STAGE_HALFS * 2)       // 55296
#define NSTG 3
#define SMEM_BYTES (NSTG * STAGE_BYTES)     // 165888

template <int EPI>
__global__ __launch_bounds__(256, 1)
void hgemm(const __half* __restrict__ A, const __half* __restrict__ Bt,
           const float* __restrict__ bias, const float* __restrict__ res,
           void* __restrict__ Cv, int M, int N, int K)
{
    extern __shared__ __half smem[];

    const int tid  = threadIdx.x;
    const int wid  = tid >> 5;
    const int lane = tid & 31;
    const int g    = lane >> 2;
    const int t4   = lane & 3;
    const int wm   = (wid >> 2) * 64;
    const int wn   = (wid & 3) * 64;
    const int brow = blockIdx.y * BM;
    const int bcol = blockIdx.x * BN;

    const uint32_t sbase = smem_u32(smem);

    const __half* Ag = A  + (size_t)brow * K;
    const __half* Bg = Bt + (size_t)bcol * K;

    auto load_stage = [&](int stage, int k0) {
        const uint32_t sA = sbase + stage * STAGE_BYTES;
        const uint32_t sB = sA + A_HALFS * 2;
        #pragma unroll
        for (int i = 0; i < 4; i++) {
            const int idx = tid + 256 * i;
            const int row = idx >> 3;
            const int col = (idx & 7) << 3;
            CP_ASYNC16(sA + (row * LDKH + col) * 2, Ag + (size_t)row * K + k0 + col);
        }
        #pragma unroll
        for (int i = 0; i < 8; i++) {
            const int idx = tid + 256 * i;
            const int row = idx >> 3;
            const int col = (idx & 7) << 3;
            CP_ASYNC16(sB + (row * LDKH + col) * 2, Bg + (size_t)row * K + k0 + col);
        }
    };

    // per-lane ldmatrix byte offsets (within stage)
    const uint32_t aOff = ((wm + (lane & 15)) * LDKH + (lane >> 4) * 8) * 2;
    const uint32_t bOff = ((wn + ((lane >> 4) * 8) + (lane & 7)) * LDKH
                           + (((lane >> 3) & 1) * 8)) * 2;

    float c[4][8][4];
    #pragma unroll
    for (int mi = 0; mi < 4; mi++)
        #pragma unroll
        for (int ni = 0; ni < 8; ni++)
            #pragma unroll
            for (int j = 0; j < 4; j++) c[mi][ni][j] = 0.f;

    const int KT = K / BK;
    load_stage(0, 0);
    CP_COMMIT();
    load_stage(1, BK);
    CP_COMMIT();

    for (int kt = 0; kt < KT; kt++) {
        CP_WAIT1();
        __syncthreads();
        if (kt + 2 < KT) load_stage((kt + 2) % NSTG, (kt + 2) * BK);
        CP_COMMIT();

        const uint32_t sA = sbase + (kt % NSTG) * STAGE_BYTES;
        const uint32_t sB = sA + A_HALFS * 2;

        #pragma unroll
        for (int kc = 0; kc < 4; kc++) {
            uint32_t a[4][4];
            #pragma unroll
            for (int mi = 0; mi < 4; mi++)
                LDM_X4(a[mi][0], a[mi][1], a[mi][2], a[mi][3],
                       sA + aOff + mi * (16 * LDKH * 2) + kc * 32);
            #pragma unroll
            for (int ni2 = 0; ni2 < 4; ni2++) {
                uint32_t b0, b1, b2, b3;
                LDM_X4(b0, b1, b2, b3,
                       sB + bOff + ni2 * (16 * LDKH * 2) + kc * 32);
                #pragma unroll
                for (int mi = 0; mi < 4; mi++) {
                    mma_f16(c[mi][2 * ni2],     a[mi][0], a[mi][1], a[mi][2], a[mi][3], b0, b1);
                    mma_f16(c[mi][2 * ni2 + 1], a[mi][0], a[mi][1], a[mi][2], a[mi][3], b2, b3);
                }
            }
        }
    }

    // ------------------------------ epilogue ---------------------------------
    #pragma unroll
    for (int mi = 0; mi < 4; mi++) {
        #pragma unroll
        for (int half = 0; half < 2; half++) {
            const int row = brow + wm + mi * 16 + g + half * 8;
            #pragma unroll
            for (int ni = 0; ni < 8; ni++) {
                const int col = bcol + wn + ni * 8 + t4 * 2;
                float v0 = c[mi][ni][half * 2 + 0] + bias[col];
                float v1 = c[mi][ni][half * 2 + 1] + bias[col + 1];
                if (EPI == 0) {
                    if (col < DIM) { v0 *= 0.125f; v1 *= 0.125f; }
                    __half* crow = (__half*)Cv + (size_t)row * N;
                    *reinterpret_cast<uint32_t*>(crow + col) = packh2(v0, v1);
                } else if (EPI == 1) {
                    v0 = gelu_f(v0); v1 = gelu_f(v1);
                    __half* crow = (__half*)Cv + (size_t)row * N;
                    *reinterpret_cast<uint32_t*>(crow + col) = packh2(v0, v1);
                } else {
                    const float2 r2 = *reinterpret_cast<const float2*>(
                        res + (size_t)row * N + col);
                    float* crow = (float*)Cv + (size_t)row * N;
                    *reinterpret_cast<float2*>(crow + col) =
                        make_float2(v0 + r2.x, v1 + r2.y);
                }
            }
        }
    }
}

// ------------------ fp16 tensor-core flash attention (causal) ----------------
// 128 threads / 4 warps, 64 queries x 64-key tiles; Q frags hoisted;
// K via ldmatrix.x4, V natural layout via ldmatrix.x4.trans;
// K/V cp.async, 3 stages, one sync per tile.
#define SLDH 72
#define KV_TILE_B (64 * SLDH * 2)            // 9216 bytes (one of K or V)
#define ATT_STAGE_B (2 * KV_TILE_B)          // 18432
#define ATT_SMEM (KV_TILE_B + NSTG * ATT_STAGE_B)   // 9216 + 55296 = 64512

__global__ __launch_bounds__(128, 1) void attn_tc_kernel(
    const __half* __restrict__ qkv, __half* __restrict__ out)
{
    extern __shared__ __half asmem[];
    const uint32_t sQ = smem_u32(asmem);

    const int bh = blockIdx.y;
    const int b = bh >> 4;
    const int h = bh & 15;
    const int q0 = blockIdx.x * 64;
    const int tid = threadIdx.x;
    const int wid = tid >> 5;
    const int lane = tid & 31;
    const int g = lane >> 2;
    const int t4 = lane & 3;
    const int rowA = wid * 16 + g;
    const int grA = q0 + rowA;
    const int grB = grA + 8;

    const int ntiles = blockIdx.x + 1;

    // K/V stage loader (cp.async)
    auto load_kv = [&](int stage, int j0) {
        const uint32_t sK = sQ + KV_TILE_B + stage * ATT_STAGE_B;
        const uint32_t sV = sK + KV_TILE_B;
        #pragma unroll
        for (int i = 0; i < 4; i++) {
            const int idx = tid + 128 * i;
            const int r = idx >> 3, c8 = (idx & 7) << 3;
            const __half* kp = qkv + (size_t)(b * SEQ + j0 + r) * (3 * DIM)
                               + DIM + h * HD + c8;
            CP_ASYNC16(sK + (r * SLDH + c8) * 2, kp);
            CP_ASYNC16(sV + (r * SLDH + c8) * 2, kp + DIM);
        }
    };

    load_kv(0, 0);
    CP_COMMIT();
    if (ntiles > 1) load_kv(1, 64);
    CP_COMMIT();

    // load Q tile into smem (plain vector loads)
    #pragma unroll
    for (int i = 0; i < 4; i++) {
        const int idx = tid + 128 * i;
        const int r = idx >> 3, c8 = (idx & 7) << 3;
        *reinterpret_cast<uint4*>(&asmem[r * SLDH + c8]) =
            *reinterpret_cast<const uint4*>(
                qkv + (size_t)(b * SEQ + q0 + r) * (3 * DIM) + h * HD + c8);
    }
    __syncthreads();

    // hoist Q fragments (loop-invariant)
    const uint32_t aOff = ((wid * 16 + (lane & 15)) * SLDH + (lane >> 4) * 8) * 2;
    uint32_t qa[4][4];
    #pragma unroll
    for (int kc = 0; kc < 4; kc++)
        LDM_X4(qa[kc][0], qa[kc][1], qa[kc][2], qa[kc][3], sQ + aOff + kc * 32);

    // per-lane K (B-frag) and V (trans B-frag) offsets
    const uint32_t kOff = (((lane >> 4) * 8 + (lane & 7)) * SLDH
                           + ((lane >> 3) & 1) * 8) * 2;
    const uint32_t vOff = ((lane & 15) * SLDH + (lane >> 4) * 8) * 2;

    float mi0 = -1e30f, mi1 = -1e30f, li0 = 0.f, li1 = 0.f;
    float o[8][4];
    #pragma unroll
    for (int ni = 0; ni < 8; ni++)
        #pragma unroll
        for (int j = 0; j < 4; j++) o[ni][j] = 0.f;

    for (int t = 0; t < ntiles; t++) {
        CP_WAIT1();
        __syncthreads();
        if (t + 2 < ntiles) load_kv((t + 2) % NSTG, (t + 2) * 64);
        CP_COMMIT();

        const uint32_t sK = sQ + KV_TILE_B + (t % NSTG) * ATT_STAGE_B;
        const uint32_t sV = sK + KV_TILE_B;
        const int j0 = t * 64;

        // ---- S = Q K^T ----
        float s[8][4];
        #pragma unroll
        for (int ni = 0; ni < 8; ni++)
            #pragma unroll
            for (int j = 0; j < 4; j++) s[ni][j] = 0.f;

        #pragma unroll
        for (int kc = 0; kc < 4; kc++) {
            #pragma unroll
            for (int ni2 = 0; ni2 < 4; ni2++) {
                uint32_t b0, b1, b2, b3;
                LDM_X4(b0, b1, b2, b3,
                       sK + kOff + ni2 * (16 * SLDH * 2) + kc * 32);
                mma_f16(s[2 * ni2],     qa[kc][0], qa[kc][1], qa[kc][2], qa[kc][3], b0, b1);
                mma_f16(s[2 * ni2 + 1], qa[kc][0], qa[kc][1], qa[kc][2], qa[kc][3], b2, b3);
            }
        }

        // ---- causal mask + online softmax (fp32) ----
        float mn0 = mi0, mn1 = mi1;
        #pragma unroll
        for (int ni = 0; ni < 8; ni++) {
            const int c0 = j0 + ni * 8 + 2 * t4;
            if (c0     > grA) s[ni][0] = -1e30f;
            if (c0 + 1 > grA) s[ni][1] = -1e30f;
            if (c0     > grB) s[ni][2] = -1e30f;
            if (c0 + 1 > grB) s[ni][3] = -1e30f;
            mn0 = fmaxf(mn0, fmaxf(s[ni][0], s[ni][1]));
            mn1 = fmaxf(mn1, fmaxf(s[ni][2], s[ni][3]));
        }
        mn0 = fmaxf(mn0, __shfl_xor_sync(0xffffffffu, mn0, 1));
        mn0 = fmaxf(mn0, __shfl_xor_sync(0xffffffffu, mn0, 2));
        mn1 = fmaxf(mn1, __shfl_xor_sync(0xffffffffu, mn1, 1));
        mn1 = fmaxf(mn1, __shfl_xor_sync(0xffffffffu, mn1, 2));

        const float corr0 = __expf(mi0 - mn0);
        const float corr1 = __expf(mi1 - mn1);
        mi0 = mn0; mi1 = mn1;

        float p[8][4];
        float ls0 = 0.f, ls1 = 0.f;
        #pragma unroll
        for (int ni = 0; ni < 8; ni++) {
            p[ni][0] = __expf(s[ni][0] - mn0);
            p[ni][1] = __expf(s[ni][1] - mn0);
            p[ni][2] = __expf(s[ni][2] - mn1);
            p[ni][3] = __expf(s[ni][3] - mn1);
            ls0 += p[ni][0] + p[ni][1];
            ls1 += p[ni][2] + p[ni][3];
        }
        ls0 += __shfl_xor_sync(0xffffffffu, ls0, 1);
        ls0 += __shfl_xor_sync(0xffffffffu, ls0, 2);
        ls1 += __shfl_xor_sync(0xffffffffu, ls1, 1);
        ls1 += __shfl_xor_sync(0xffffffffu, ls1, 2);
        li0 = li0 * corr0 + ls0;
        li1 = li1 * corr1 + ls1;

        #pragma unroll
        for (int ni = 0; ni < 8; ni++) {
            o[ni][0] *= corr0; o[ni][1] *= corr0;
            o[ni][2] *= corr1; o[ni][3] *= corr1;
        }

        // ---- O += P V (P packed reg->reg; V frags via ldmatrix.trans) ----
        #pragma unroll
        for (int kc = 0; kc < 4; kc++) {
            const uint32_t a0 = packh2(p[2 * kc][0],     p[2 * kc][1]);
            const uint32_t a1 = packh2(p[2 * kc][2],     p[2 * kc][3]);
            const uint32_t a2 = packh2(p[2 * kc + 1][0], p[2 * kc + 1][1]);
            const uint32_t a3 = packh2(p[2 * kc + 1][2], p[2 * kc + 1][3]);
            #pragma unroll
            for (int ni2 = 0; ni2 < 4; ni2++) {
                uint32_t b0, b1, b2, b3;
                LDM_X4_T(b0, b1, b2, b3,
                         sV + vOff + kc * (16 * SLDH * 2) + ni2 * 32);
                mma_f16(o[2 * ni2],     a0, a1, a2, a3, b0, b1);
                mma_f16(o[2 * ni2 + 1], a0, a1, a2, a3, b2, b3);
            }
        }
    }

    const float inv0 = 1.0f / li0;
    const float inv1 = 1.0f / li1;
    __half* orow0 = out + (size_t)(b * SEQ + grA) * DIM + h * HD;
    __half* orow1 = out + (size_t)(b * SEQ + grB) * DIM + h * HD;
    #pragma unroll
    for (int ni = 0; ni < 8; ni++) {
        const int d = ni * 8 + 2 * t4;
        *reinterpret_cast<uint32_t*>(orow0 + d) = packh2(o[ni][0] * inv0, o[ni][1] * inv0);
        *reinterpret_cast<uint32_t*>(orow1 + d) = packh2(o[ni][2] * inv1, o[ni][3] * inv1);
    }
}

// ------------------------------ launcher -------------------------------------
extern "C" void kernel_launch(void* const* d_in, const int* in_sizes, int n_in,
                              void* d_out, int out_size)
{
    (void)in_sizes; (void)n_in; (void)out_size;
    const float* x    = (const float*)d_in[0];
    const float* ln1s = (const float*)d_in[2];
    const float* ln1b = (const float*)d_in[3];
    const float* ln2s = (const float*)d_in[4];
    const float* ln2b = (const float*)d_in[5];
    const float* wqkv = (const float*)d_in[6];
    const float* bqkv = (const float*)d_in[7];
    const float* wap  = (const float*)d_in[8];
    const float* bap  = (const float*)d_in[9];
    const float* wfc  = (const float*)d_in[10];
    const float* bfc  = (const float*)d_in[11];
    const float* wmp  = (const float*)d_in[12];
    const float* bmp  = (const float*)d_in[13];
    float* out = (float*)d_out;

    __half *lnh, *qkvh, *attnh, *fch, *wqkvT, *wapT, *wfcT, *wmpT;
    float *x2;
    cudaGetSymbolAddress((void**)&lnh,   g_lnh);
    cudaGetSymbolAddress((void**)&qkvh,  g_qkvh);
    cudaGetSymbolAddress((void**)&attnh, g_attnh);
    cudaGetSymbolAddress((void**)&x2,    g_x2);
    cudaGetSymbolAddress((void**)&fch,   g_fch);
    cudaGetSymbolAddress((void**)&wqkvT, g_wqkvT);
    cudaGetSymbolAddress((void**)&wapT,  g_wapT);
    cudaGetSymbolAddress((void**)&wfcT,  g_wfcT);
    cudaGetSymbolAddress((void**)&wmpT,  g_wmpT);

    cudaFuncSetAttribute(hgemm<0>, cudaFuncAttributeMaxDynamicSharedMemorySize, SMEM_BYTES);
    cudaFuncSetAttribute(hgemm<1>, cudaFuncAttributeMaxDynamicSharedMemorySize, SMEM_BYTES);
    cudaFuncSetAttribute(hgemm<2>, cudaFuncAttributeMaxDynamicSharedMemorySize, SMEM_BYTES);
    cudaFuncSetAttribute(attn_tc_kernel, cudaFuncAttributeMaxDynamicSharedMemorySize, ATT_SMEM);

    dim3 tb(32, 8);
    transpose_kernel<<<dim3(3 * DIM / 32, DIM / 32), tb>>>(wqkv, wqkvT, DIM, 3 * DIM);
    transpose_kernel<<<dim3(DIM / 32, DIM / 32),     tb>>>(wap,  wapT,  DIM, DIM);
    transpose_kernel<<<dim3(DFF / 32, DIM / 32),     tb>>>(wfc,  wfcT,  DIM, DFF);
    transpose_kernel<<<dim3(DIM / 32, DFF / 32),     tb>>>(wmp,  wmpT,  DFF, DIM);

    ln_kernel<<<MROWS, 256>>>(x, ln1s, ln1b, lnh);
    hgemm<0><<<dim3(3 * DIM / BN, MROWS / BM), 256, SMEM_BYTES>>>(
        lnh, wqkvT, bqkv, nullptr, qkvh, MROWS, 3 * DIM, DIM);
    attn_tc_kernel<<<dim3(SEQ / 64, BSZ * NH), 128, ATT_SMEM>>>(qkvh, attnh);
    hgemm<2><<<dim3(DIM / BN, MROWS / BM), 256, SMEM_BYTES>>>(
        attnh, wapT, bap, x, x2, MROWS, DIM, DIM);
    ln_kernel<<<MROWS, 256>>>(x2, ln2s, ln2b, lnh);
    hgemm<1><<<dim3(DFF / BN, MROWS / BM), 256, SMEM_BYTES>>>(
        lnh, wfcT, bfc, nullptr, fch, MROWS, DFF, DIM);
    hgemm<2><<<dim3(DIM / BN, MROWS / BM), 256, SMEM_BYTES>>>(
        fch, wmpT, bmp, x2, out, MROWS, DIM, DFF);
}